// round 7
// baseline (speedup 1.0000x reference)
#include <cuda_runtime.h>
#include <cuda_fp16.h>
#include <stdint.h>
#include <math.h>

#define B_  2
#define N_  16384
#define M_  2048
#define D_  256
#define R_  (B_*N_)
#define RQ_ (B_*M_)
#define NSPLIT 4
#define KR_ (N_/NSPLIT)          // 4096 contraction per wv split
#define NMT 16                   // number of m-tiles (M_/128)
#define STAGE_BYTES 32768        // logits/proj: Ah(8K) Al(8K) Bh(8K) Bl(8K)
#define DYN_SMEM (3*STAGE_BYTES)
#define STAGE_WV 24576           // wv: Ah(8K) Bh(8K) Bl(8K)
#define DYN_SMEM_WV (3*STAGE_WV)

// ======================= device scratch =====================================
__device__ __align__(16) float  g_r[R_*3];
__device__ __align__(16) __half g_ph [(size_t)R_*D_],  g_pl [(size_t)R_*D_];
__device__ __align__(16) __half g_vfh[(size_t)RQ_*D_], g_vfl[(size_t)RQ_*D_];
__device__ __align__(16) __half g_wqTh[D_*D_], g_wqTl[D_*D_];
__device__ __align__(16) __half g_wkTh[D_*D_], g_wkTl[D_*D_];
__device__ __align__(16) __half g_wvTh[D_*D_], g_wvTl[D_*D_];
__device__ __align__(16) __half g_qh [(size_t)RQ_*D_], g_ql [(size_t)RQ_*D_];
__device__ __align__(16) __half g_kpvh[(size_t)R_*D_], g_kpvl[(size_t)R_*D_];
__device__ __align__(16) float  g_v[(size_t)R_*D_];
__device__ __align__(16) __half g_vth[(size_t)B_*D_*N_], g_vtl[(size_t)B_*D_*N_];
__device__ __align__(16) float  g_logits[(size_t)B_*M_*N_];   // 256 MB (scaled)
__device__ __align__(16) float  g_pmax[NMT*B_*N_], g_psum[NMT*B_*N_];
__device__ __align__(16) float  g_cstat[B_*N_];
__device__ __align__(16) float  g_part[(size_t)B_*NSPLIT*M_*D_];

// ======================= small helpers ======================================
__device__ __forceinline__ uint32_t smem_u32(const void* p) {
    uint32_t a;
    asm("{ .reg .u64 t; cvta.to.shared.u64 t, %1; cvt.u32.u64 %0, t; }" : "=r"(a) : "l"(p));
    return a;
}
__device__ __forceinline__ void cp16(uint32_t dst, const void* src) {
    asm volatile("cp.async.cg.shared.global [%0], [%1], 16;" :: "r"(dst), "l"(src));
}
#define CP_COMMIT() asm volatile("cp.async.commit_group;" ::: "memory")
#define CP_WAIT0()  asm volatile("cp.async.wait_group 0;" ::: "memory")
#define CP_WAIT1()  asm volatile("cp.async.wait_group 1;" ::: "memory")

__device__ __forceinline__ void ldsm_x4(uint32_t& r0, uint32_t& r1, uint32_t& r2, uint32_t& r3,
                                        uint32_t addr) {
    asm volatile("ldmatrix.sync.aligned.m8n8.x4.shared.b16 {%0,%1,%2,%3}, [%4];"
                 : "=r"(r0), "=r"(r1), "=r"(r2), "=r"(r3) : "r"(addr));
}
__device__ __forceinline__ void mma16816(float* c, const uint32_t* a, uint32_t b0, uint32_t b1) {
    asm volatile(
        "mma.sync.aligned.m16n8k16.row.col.f32.f16.f16.f32 "
        "{%0,%1,%2,%3}, {%4,%5,%6,%7}, {%8,%9}, {%0,%1,%2,%3};"
        : "+f"(c[0]), "+f"(c[1]), "+f"(c[2]), "+f"(c[3])
        : "r"(a[0]), "r"(a[1]), "r"(a[2]), "r"(a[3]), "r"(b0), "r"(b1));
}

// swizzled byte offset in a 128-row x 32-half tile (64B rows)
__device__ __forceinline__ uint32_t sw(int row, int c16) {
    return (uint32_t)(row * 64 + ((c16 ^ ((row ^ (row >> 2)) & 3)) << 4));
}

// fast exp, FFMA-only (no MUFU). Valid for x <= 0 (args here are always <= 0).
__device__ __forceinline__ float fexp(float x) {
    x = fmaxf(x, -80.0f);
    float nf = fmaf(x, 1.4426950408889634f, 12582912.0f);
    int  i   = __float_as_int(nf) - 0x4B400000;
    float n  = nf - 12582912.0f;
    float f  = fmaf(n, -0.693145751953125f, x);
    f        = fmaf(n, -1.42860682030941723e-6f, f);
    float p = 1.3888889e-3f;
    p = fmaf(p, f, 8.3333333e-3f);
    p = fmaf(p, f, 4.1666668e-2f);
    p = fmaf(p, f, 1.6666667e-1f);
    p = fmaf(p, f, 5.0e-1f);
    p = fmaf(p, f, 1.0f);
    p = fmaf(p, f, 1.0f);
    return p * __int_as_float((i + 127) << 23);
}

// ======================= 3-pass MMA stage, 64x64 warp tiles ==================
// stage layout: Ah @ +0, Al @ +8192, Bh @ +16384, Bl @ +24576
__device__ __forceinline__ void compute_stage64(uint32_t sb, int mw0, int nw0,
                                                float cacc[4][8][4], int lane) {
    int arow = lane & 15, asel = lane >> 4;
    int brow = (lane & 7) + ((lane >> 4) << 3), bsel = (lane >> 3) & 1;
#pragma unroll
    for (int ks = 0; ks < 2; ks++) {
        uint32_t ah[4][4], bh[4][4];
#pragma unroll
        for (int mi = 0; mi < 4; mi++)
            ldsm_x4(ah[mi][0], ah[mi][1], ah[mi][2], ah[mi][3],
                    sb + sw(mw0 + mi*16 + arow, ks*2 + asel));
#pragma unroll
        for (int nb = 0; nb < 4; nb++)
            ldsm_x4(bh[nb][0], bh[nb][1], bh[nb][2], bh[nb][3],
                    sb + 16384 + sw(nw0 + nb*16 + brow, ks*2 + bsel));
#pragma unroll
        for (int mi = 0; mi < 4; mi++)
#pragma unroll
            for (int nj = 0; nj < 8; nj++)
                mma16816(cacc[mi][nj], ah[mi], bh[nj>>1][(nj&1)*2], bh[nj>>1][(nj&1)*2+1]);

        uint32_t bl[4][4];
#pragma unroll
        for (int nb = 0; nb < 4; nb++)
            ldsm_x4(bl[nb][0], bl[nb][1], bl[nb][2], bl[nb][3],
                    sb + 24576 + sw(nw0 + nb*16 + brow, ks*2 + bsel));
#pragma unroll
        for (int mi = 0; mi < 4; mi++)
#pragma unroll
            for (int nj = 0; nj < 8; nj++)
                mma16816(cacc[mi][nj], ah[mi], bl[nj>>1][(nj&1)*2], bl[nj>>1][(nj&1)*2+1]);

        uint32_t al[4][4];
#pragma unroll
        for (int mi = 0; mi < 4; mi++)
            ldsm_x4(al[mi][0], al[mi][1], al[mi][2], al[mi][3],
                    sb + 8192 + sw(mw0 + mi*16 + arow, ks*2 + asel));
#pragma unroll
        for (int mi = 0; mi < 4; mi++)
#pragma unroll
            for (int nj = 0; nj < 8; nj++)
                mma16816(cacc[mi][nj], al[mi], bh[nj>>1][(nj&1)*2], bh[nj>>1][(nj&1)*2+1]);
    }
}

// ======================= 2-pass MMA stage (wv, 8 warps 64x32) ================
__device__ __forceinline__ void compute_stage_wv(uint32_t sb, int mw0, int nw0,
                                                 float cacc[4][4][4], int lane) {
    int arow = lane & 15, asel = lane >> 4;
    int brow = (lane & 7) + ((lane >> 4) << 3), bsel = (lane >> 3) & 1;
#pragma unroll
    for (int ks = 0; ks < 2; ks++) {
        uint32_t ah[4][4], bh[2][4], bl[2][4];
#pragma unroll
        for (int mi = 0; mi < 4; mi++)
            ldsm_x4(ah[mi][0], ah[mi][1], ah[mi][2], ah[mi][3],
                    sb + sw(mw0 + mi*16 + arow, ks*2 + asel));
#pragma unroll
        for (int nb = 0; nb < 2; nb++)
            ldsm_x4(bh[nb][0], bh[nb][1], bh[nb][2], bh[nb][3],
                    sb + 8192 + sw(nw0 + nb*16 + brow, ks*2 + bsel));
#pragma unroll
        for (int mi = 0; mi < 4; mi++)
#pragma unroll
            for (int nj = 0; nj < 4; nj++)
                mma16816(cacc[mi][nj], ah[mi], bh[nj>>1][(nj&1)*2], bh[nj>>1][(nj&1)*2+1]);
#pragma unroll
        for (int nb = 0; nb < 2; nb++)
            ldsm_x4(bl[nb][0], bl[nb][1], bl[nb][2], bl[nb][3],
                    sb + 16384 + sw(nw0 + nb*16 + brow, ks*2 + bsel));
#pragma unroll
        for (int mi = 0; mi < 4; mi++)
#pragma unroll
            for (int nj = 0; nj < 4; nj++)
                mma16816(cacc[mi][nj], ah[mi], bl[nj>>1][(nj&1)*2], bl[nj>>1][(nj&1)*2+1]);
    }
}

// cp.async staging of a full 3-pass stage (A hi/lo + B hi/lo), 128 threads
__device__ __forceinline__ void stage4_128(uint32_t sb,
                                           const __half* __restrict__ Ah, const __half* __restrict__ Al,
                                           size_t ar0, int lda,
                                           const __half* __restrict__ Bh, const __half* __restrict__ Bl,
                                           size_t br0, int ldb, int k0) {
    int t = threadIdx.x;
#pragma unroll
    for (int i = 0; i < 4; i++) {
        int c = t + 128*i;
        int row = c >> 2, c16 = c & 3;
        uint32_t so = sw(row, c16);
        size_t ka = (size_t)k0 + c16*8;
        cp16(sb + so,         Ah + (ar0 + row)*(size_t)lda + ka);
        cp16(sb + 8192 + so,  Al + (ar0 + row)*(size_t)lda + ka);
        cp16(sb + 16384 + so, Bh + (br0 + row)*(size_t)ldb + ka);
        cp16(sb + 24576 + so, Bl + (br0 + row)*(size_t)ldb + ka);
    }
}

// ======================= K0: positional path ================================
__global__ void pv_relu_kernel(const float* __restrict__ p_xyz, const float* __restrict__ v_xyz,
                               const float* __restrict__ Wp1, const float* __restrict__ bp1,
                               const float* __restrict__ ln_w, const float* __restrict__ ln_b) {
    int idx = blockIdx.x * blockDim.x + threadIdx.x;
    if (idx >= R_) return;
    int b = idx / N_;
    float d0 = fabsf(p_xyz[idx*3+0] - v_xyz[b*3+0]);
    float d1 = fabsf(p_xyz[idx*3+1] - v_xyz[b*3+1]);
    float d2 = fabsf(p_xyz[idx*3+2] - v_xyz[b*3+2]);
    float h0 = d0*Wp1[0] + d1*Wp1[3] + d2*Wp1[6] + bp1[0];
    float h1 = d0*Wp1[1] + d1*Wp1[4] + d2*Wp1[7] + bp1[1];
    float h2 = d0*Wp1[2] + d1*Wp1[5] + d2*Wp1[8] + bp1[2];
    float mu = (h0 + h1 + h2) * (1.0f/3.0f);
    float e0 = h0-mu, e1 = h1-mu, e2 = h2-mu;
    float inv = rsqrtf((e0*e0 + e1*e1 + e2*e2) * (1.0f/3.0f) + 1e-5f);
    g_r[idx*3+0] = fmaxf(e0*inv*ln_w[0] + ln_b[0], 0.0f);
    g_r[idx*3+1] = fmaxf(e1*inv*ln_w[1] + ln_b[1], 0.0f);
    g_r[idx*3+2] = fmaxf(e2*inv*ln_w[2] + ln_b[2], 0.0f);
}

// ======================= prep: all hi/lo splits (one launch) =================
#define NP2 ((size_t)R_*D_/2)
#define NV2 ((size_t)RQ_*D_/2)
__global__ void splitall_kernel(const float* __restrict__ P, const float* __restrict__ VF) {
    size_t i = (size_t)blockIdx.x * blockDim.x + threadIdx.x;
    const float* src; __half *hi, *lo; size_t j;
    if (i < NP2)                 { src = P;  hi = g_ph;  lo = g_pl;  j = i; }
    else if (i < NP2 + NV2)      { src = VF; hi = g_vfh; lo = g_vfl; j = i - NP2; }
    else return;
    float2 v = reinterpret_cast<const float2*>(src)[j];
    __half h0 = __float2half_rn(v.x), h1 = __float2half_rn(v.y);
    __half l0 = __float2half_rn(v.x - __half2float(h0));
    __half l1 = __float2half_rn(v.y - __half2float(h1));
    reinterpret_cast<__half2*>(hi)[j] = __halves2half2(h0, h1);
    reinterpret_cast<__half2*>(lo)[j] = __halves2half2(l0, l1);
}

__global__ void wtsplitall_kernel(const float* __restrict__ Wq, const float* __restrict__ Wk,
                                  const float* __restrict__ Wv) {
    int i = blockIdx.x * blockDim.x + threadIdx.x;   // 3*65536
    int w = i >> 16, rem = i & 65535;
    int d = rem >> 8, c = rem & 255;
    const float* W = (w == 0) ? Wq : (w == 1) ? Wk : Wv;
    __half* Th = (w == 0) ? g_wqTh : (w == 1) ? g_wkTh : g_wvTh;
    __half* Tl = (w == 0) ? g_wqTl : (w == 1) ? g_wkTl : g_wvTl;
    float v = W[rem];
    __half h = __float2half_rn(v);
    Th[c*256 + d] = h;
    Tl[c*256 + d] = __float2half_rn(v - __half2float(h));
}

// ======================= fused projections (HMMA, 128 thr, 64x64 warps) ======
// z=0: q = vf@Wq + bq -> qh/ql ; z=1: kpv = p@Wk + bk + pv ; z=2: v (fp32)
__global__ __launch_bounds__(128, 2)
void proj_mma_kernel(const float* __restrict__ bq, const float* __restrict__ bk,
                     const float* __restrict__ bv, const float* __restrict__ Wp2,
                     const float* __restrict__ bp2) {
    int mode = blockIdx.z;
    if (mode == 0 && blockIdx.y >= RQ_/128) return;
    extern __shared__ char dyn[];
    uint32_t sb = smem_u32(dyn);
    const __half *Xh, *Xl, *WTh, *WTl; const float* bias;
    if (mode == 0)      { Xh = g_vfh; Xl = g_vfl; WTh = g_wqTh; WTl = g_wqTl; bias = bq; }
    else if (mode == 1) { Xh = g_ph;  Xl = g_pl;  WTh = g_wkTh; WTl = g_wkTl; bias = bk; }
    else                { Xh = g_ph;  Xl = g_pl;  WTh = g_wvTh; WTl = g_wvTl; bias = bv; }

    size_t row0 = (size_t)blockIdx.y * 128;
    int c0 = blockIdx.x * 128;
    int lane = threadIdx.x & 31, wid = threadIdx.x >> 5;
    int mw0 = (wid >> 1) * 64, nw0 = (wid & 1) * 64;
    float cacc[4][8][4] = {};

    stage4_128(sb + 0*STAGE_BYTES, Xh, Xl, row0, D_, WTh, WTl, (size_t)c0, D_, 0);  CP_COMMIT();
    stage4_128(sb + 1*STAGE_BYTES, Xh, Xl, row0, D_, WTh, WTl, (size_t)c0, D_, 32); CP_COMMIT();
#pragma unroll 1
    for (int s = 0; s < 8; s++) {
        if (s < 7) CP_WAIT1(); else CP_WAIT0();
        __syncthreads();
        if (s + 2 < 8) {
            stage4_128(sb + ((s+2)%3)*STAGE_BYTES, Xh, Xl, row0, D_, WTh, WTl, (size_t)c0, D_, (s+2)*32);
            CP_COMMIT();
        }
        compute_stage64(sb + (s%3)*STAGE_BYTES, mw0, nw0, cacc, lane);
    }

    int g = lane >> 2, tg = lane & 3;
#pragma unroll
    for (int mi = 0; mi < 4; mi++) {
#pragma unroll
        for (int half_m = 0; half_m < 2; half_m++) {
            size_t r = row0 + mw0 + mi*16 + g + half_m*8;
            float q0 = 0.f, q1 = 0.f, q2 = 0.f;
            if (mode == 1) { q0 = g_r[r*3+0]; q1 = g_r[r*3+1]; q2 = g_r[r*3+2]; }
#pragma unroll
            for (int nj = 0; nj < 8; nj++) {
#pragma unroll
                for (int e = 0; e < 2; e++) {
                    int c = c0 + nw0 + nj*8 + tg*2 + e;
                    float v = cacc[mi][nj][half_m*2 + e] + bias[c];
                    if (mode == 1) v += q0*Wp2[c] + q1*Wp2[D_+c] + q2*Wp2[2*D_+c] + bp2[c];
                    if (mode == 2) { g_v[r*D_ + c] = v; }
                    else {
                        __half h = __float2half_rn(v);
                        __half l = __float2half_rn(v - __half2float(h));
                        if (mode == 0) { g_qh[r*D_+c] = h;   g_ql[r*D_+c] = l; }
                        else           { g_kpvh[r*D_+c] = h; g_kpvl[r*D_+c] = l; }
                    }
                }
            }
        }
    }
}

// ======================= V transpose + split =================================
__global__ void vtrans_kernel() {
    __shared__ float tl[32][33];
    int n0 = blockIdx.x * 32, d0 = blockIdx.y * 32, b = blockIdx.z;
    int tx = threadIdx.x, ty = threadIdx.y;
#pragma unroll
    for (int k = 0; k < 4; k++)
        tl[ty + k*8][tx] = g_v[(size_t)(b*N_ + n0 + ty + k*8)*D_ + d0 + tx];
    __syncthreads();
#pragma unroll
    for (int k = 0; k < 4; k++) {
        int d = d0 + ty + k*8;
        float v = tl[tx][ty + k*8];
        __half h = __float2half_rn(v);
        size_t o = (size_t)(b*D_ + d)*N_ + n0 + tx;
        g_vth[o] = h;
        g_vtl[o] = __float2half_rn(v - __half2float(h));
    }
}

// ======================= logits (HMMA, 128 thr, 64x64 warps) + stats =========
__global__ __launch_bounds__(128, 2)
void logits_mma_kernel() {
    extern __shared__ char dyn[];
    uint32_t sb = smem_u32(dyn);
    int b = blockIdx.z;
    int n0 = blockIdx.x * 128, m0 = blockIdx.y * 128;
    size_t ar0 = (size_t)b*M_ + m0, br0 = (size_t)b*N_ + n0;
    int lane = threadIdx.x & 31, wid = threadIdx.x >> 5;
    int mw0 = (wid >> 1) * 64, nw0 = (wid & 1) * 64;
    float cacc[4][8][4] = {};

    stage4_128(sb + 0*STAGE_BYTES, g_qh, g_ql, ar0, D_, g_kpvh, g_kpvl, br0, D_, 0);  CP_COMMIT();
    stage4_128(sb + 1*STAGE_BYTES, g_qh, g_ql, ar0, D_, g_kpvh, g_kpvl, br0, D_, 32); CP_COMMIT();
#pragma unroll 1
    for (int s = 0; s < 8; s++) {
        if (s < 7) CP_WAIT1(); else CP_WAIT0();
        __syncthreads();
        if (s + 2 < 8) {
            stage4_128(sb + ((s+2)%3)*STAGE_BYTES, g_qh, g_ql, ar0, D_, g_kpvh, g_kpvl, br0, D_, (s+2)*32);
            CP_COMMIT();
        }
        compute_stage64(sb + (s%3)*STAGE_BYTES, mw0, nw0, cacc, lane);
    }

    // scale accumulators (logits are stored pre-scaled)
#pragma unroll
    for (int mi = 0; mi < 4; mi++)
#pragma unroll
        for (int nj = 0; nj < 8; nj++)
#pragma unroll
            for (int e = 0; e < 4; e++) cacc[mi][nj][e] *= 0.0625f;

    int g = lane >> 2, tg = lane & 3;
    float* L = g_logits + (size_t)b*M_*N_;
#pragma unroll
    for (int mi = 0; mi < 4; mi++)
#pragma unroll
        for (int nj = 0; nj < 8; nj++) {
            int m = m0 + mw0 + mi*16 + g;
            int n = n0 + nw0 + nj*8 + tg*2;
            float2 v0 = { cacc[mi][nj][0], cacc[mi][nj][1] };
            float2 v1 = { cacc[mi][nj][2], cacc[mi][nj][3] };
            *reinterpret_cast<float2*>(&L[(size_t)m*N_ + n])     = v0;
            *reinterpret_cast<float2*>(&L[(size_t)(m+8)*N_ + n]) = v1;
        }

    // per-column (over 128 m rows of this tile) max + sumexp partials
    __syncthreads();              // smem (dyn) free for reuse now
    float* smax = reinterpret_cast<float*>(dyn);        // [2][128]
    float* ssum = smax + 256;                            // [2][128]
#pragma unroll
    for (int nj = 0; nj < 8; nj++) {
#pragma unroll
        for (int ec = 0; ec < 2; ec++) {
            float mx = -1e30f;
#pragma unroll
            for (int mi = 0; mi < 4; mi++) {
                mx = fmaxf(mx, cacc[mi][nj][ec]);
                mx = fmaxf(mx, cacc[mi][nj][2 + ec]);
            }
            mx = fmaxf(mx, __shfl_xor_sync(0xFFFFFFFFu, mx, 4));
            mx = fmaxf(mx, __shfl_xor_sync(0xFFFFFFFFu, mx, 8));
            mx = fmaxf(mx, __shfl_xor_sync(0xFFFFFFFFu, mx, 16));
            float s = 0.0f;
#pragma unroll
            for (int mi = 0; mi < 4; mi++) {
                s += fexp(cacc[mi][nj][ec]     - mx);
                s += fexp(cacc[mi][nj][2 + ec] - mx);
            }
            s += __shfl_xor_sync(0xFFFFFFFFu, s, 4);
            s += __shfl_xor_sync(0xFFFFFFFFu, s, 8);
            s += __shfl_xor_sync(0xFFFFFFFFu, s, 16);
            if (g == 0) {
                int nc = (wid & 1)*64 + nj*8 + tg*2 + ec;
                smax[(wid >> 1)*128 + nc] = mx;
                ssum[(wid >> 1)*128 + nc] = s;
            }
        }
    }
    __syncthreads();
    int t = threadIdx.x;
    {
        float m0v = smax[t], m1v = smax[128 + t];
        float s0  = ssum[t], s1  = ssum[128 + t];
        float mm = fmaxf(m0v, m1v);
        float ss = s0 * fexp(m0v - mm) + s1 * fexp(m1v - mm);
        int col = b*N_ + n0 + t;
        g_pmax[blockIdx.y*(B_*N_) + col] = mm;
        g_psum[blockIdx.y*(B_*N_) + col] = ss;
    }
}

// ======================= stats reduce over m-tiles ===========================
__global__ void cstat_reduce_kernel() {
    int col = blockIdx.x * blockDim.x + threadIdx.x;   // 0..B*N-1
    float mx = -1e30f, sum = 0.0f;
#pragma unroll
    for (int ti = 0; ti < NMT; ti++) {
        float m2 = g_pmax[ti*(B_*N_) + col];
        float s2 = g_psum[ti*(B_*N_) + col];
        if (m2 > mx) { sum = sum * fexp(mx - m2) + s2; mx = m2; }
        else         { sum += s2 * fexp(m2 - mx); }
    }
    g_cstat[col] = mx + __logf(sum);
}

// ======================= weighted value (HMMA 2-pass, split-K, fused exp) ====
__global__ __launch_bounds__(256, 2)
void wv_mma_kernel() {
    extern __shared__ char dyn[];
    uint32_t sb = smem_u32(dyn);
    int z = blockIdx.z, b = z >> 2, sp = z & 3;
    int d0 = blockIdx.x * 128, m0 = blockIdx.y * 128;
    int kbeg = sp * KR_;
    const float* L  = g_logits + (size_t)b*M_*N_;
    const float* CS = g_cstat + b*N_;
    size_t br0 = (size_t)b*D_ + d0;
    int t = threadIdx.x, lane = t & 31, wid = t >> 5;
    int mw0 = (wid >> 2) * 64, nw0 = (wid & 3) * 32;
    float cacc[4][4][4] = {};

    int rows[2], c16s[2];
#pragma unroll
    for (int i = 0; i < 2; i++) { int c = t + 256*i; rows[i] = c >> 2; c16s[i] = c & 3; }

    float4 ra[2][2];
    // prologue: LDG A(0); cp.async B(0), B(1)
#pragma unroll
    for (int i = 0; i < 2; i++) {
        size_t base = (size_t)(m0 + rows[i])*N_ + kbeg + c16s[i]*8;
        ra[i][0] = *reinterpret_cast<const float4*>(&L[base]);
        ra[i][1] = *reinterpret_cast<const float4*>(&L[base + 4]);
    }
#pragma unroll
    for (int st = 0; st < 2; st++) {
        uint32_t bufB = sb + st*STAGE_WV;
#pragma unroll
        for (int i = 0; i < 2; i++) {
            uint32_t so = sw(rows[i], c16s[i]);
            size_t ka = (size_t)(kbeg + st*32) + c16s[i]*8;
            cp16(bufB + 8192  + so, g_vth + (br0 + rows[i])*(size_t)N_ + ka);
            cp16(bufB + 16384 + so, g_vtl + (br0 + rows[i])*(size_t)N_ + ka);
        }
        CP_COMMIT();
    }

    const int NCH = KR_ / 32;   // 128
#pragma unroll 1
    for (int s = 0; s < NCH; s++) {
        uint32_t buf  = sb + (s%3)*STAGE_WV;
        char*    bufp = dyn + (s%3)*STAGE_WV;
        if (s < NCH-1) CP_WAIT1(); else CP_WAIT0();
        // transform + STS A(s): weights hi only (2-pass drops w_lo)
#pragma unroll
        for (int i = 0; i < 2; i++) {
            int kabs = kbeg + s*32 + c16s[i]*8;
            float4 cs0 = *reinterpret_cast<const float4*>(&CS[kabs]);
            float4 cs1 = *reinterpret_cast<const float4*>(&CS[kabs + 4]);
            float w[8];
            w[0] = fexp(ra[i][0].x - cs0.x); w[1] = fexp(ra[i][0].y - cs0.y);
            w[2] = fexp(ra[i][0].z - cs0.z); w[3] = fexp(ra[i][0].w - cs0.w);
            w[4] = fexp(ra[i][1].x - cs1.x); w[5] = fexp(ra[i][1].y - cs1.y);
            w[6] = fexp(ra[i][1].z - cs1.z); w[7] = fexp(ra[i][1].w - cs1.w);
            uint32_t hi[4];
#pragma unroll
            for (int j = 0; j < 4; j++) {
                __half h0 = __float2half_rn(w[2*j]), h1 = __float2half_rn(w[2*j+1]);
                hi[j] = (uint32_t)__half_as_ushort(h0) | ((uint32_t)__half_as_ushort(h1) << 16);
            }
            uint32_t so = sw(rows[i], c16s[i]);
            *reinterpret_cast<uint4*>(bufp + so) = make_uint4(hi[0], hi[1], hi[2], hi[3]);
        }
        __syncthreads();
        if (s + 1 < NCH) {
            int kn = kbeg + (s+1)*32;
#pragma unroll
            for (int i = 0; i < 2; i++) {
                size_t base = (size_t)(m0 + rows[i])*N_ + kn + c16s[i]*8;
                ra[i][0] = *reinterpret_cast<const float4*>(&L[base]);
                ra[i][1] = *reinterpret_cast<const float4*>(&L[base + 4]);
            }
        }
        if (s + 2 < NCH) {
            uint32_t nbuf = sb + ((s+2)%3)*STAGE_WV;
            int kn2 = kbeg + (s+2)*32;
#pragma unroll
            for (int i = 0; i < 2; i++) {
                uint32_t so = sw(rows[i], c16s[i]);
                size_t ka = (size_t)kn2 + c16s[i]*8;
                cp16(nbuf + 8192  + so, g_vth + (br0 + rows[i])*(size_t)N_ + ka);
                cp16(nbuf + 16384 + so, g_vtl + (br0 + rows[i])*(size_t)N_ + ka);
            }
            CP_COMMIT();
        }
        compute_stage_wv(buf, mw0, nw0, cacc, lane);
    }

    int g = lane >> 2, tg = lane & 3;
    float* P = g_part + (size_t)z*M_*D_;
#pragma unroll
    for (int mi = 0; mi < 4; mi++)
#pragma unroll
        for (int nj = 0; nj < 4; nj++) {
            int m = m0 + mw0 + mi*16 + g;
            int d = d0 + nw0 + nj*8 + tg*2;
            float2 v0 = { cacc[mi][nj][0], cacc[mi][nj][1] };
            float2 v1 = { cacc[mi][nj][2], cacc[mi][nj][3] };
            *reinterpret_cast<float2*>(&P[(size_t)m*D_ + d])     = v0;
            *reinterpret_cast<float2*>(&P[(size_t)(m+8)*D_ + d]) = v1;
        }
}

// ======================= reduce + residual ===================================
__global__ void reduce_kernel(const float* __restrict__ Vf, float* __restrict__ out) {
    int i4 = blockIdx.x * blockDim.x + threadIdx.x;   // RQ_*D_/4
    int row = i4 >> 6;
    int b = row >> 11;
    int mrow = row & (M_ - 1);
    int d4 = i4 & 63;
    float4 acc = reinterpret_cast<const float4*>(Vf)[i4];
#pragma unroll
    for (int s = 0; s < NSPLIT; s++) {
        size_t pi = ((size_t)(b*NSPLIT + s)*M_ + mrow)*64 + d4;
        float4 p = reinterpret_cast<const float4*>(g_part)[pi];
        acc.x += p.x; acc.y += p.y; acc.z += p.z; acc.w += p.w;
    }
    reinterpret_cast<float4*>(out)[i4] = acc;
}

// ======================= launcher ============================================
extern "C" void kernel_launch(void* const* d_in, const int* in_sizes, int n_in,
                              void* d_out, int out_size) {
    const float* p_xyz      = (const float*)d_in[0];
    const float* v_xyz      = (const float*)d_in[1];
    const float* p_features = (const float*)d_in[2];
    const float* v_features = (const float*)d_in[3];
    const float* Wq  = (const float*)d_in[4];
    const float* bq  = (const float*)d_in[5];
    const float* Wk  = (const float*)d_in[6];
    const float* bk  = (const float*)d_in[7];
    const float* Wv  = (const float*)d_in[8];
    const float* bv  = (const float*)d_in[9];
    const float* Wp1 = (const float*)d_in[10];
    const float* bp1 = (const float*)d_in[11];
    const float* ln_w = (const float*)d_in[12];
    const float* ln_b = (const float*)d_in[13];
    const float* Wp2 = (const float*)d_in[14];
    const float* bp2 = (const float*)d_in[15];
    float* out = (float*)d_out;

    static int attr_done = 0;
    if (!attr_done) {
        cudaFuncSetAttribute(proj_mma_kernel,   cudaFuncAttributeMaxDynamicSharedMemorySize, DYN_SMEM);
        cudaFuncSetAttribute(logits_mma_kernel, cudaFuncAttributeMaxDynamicSharedMemorySize, DYN_SMEM);
        cudaFuncSetAttribute(wv_mma_kernel,     cudaFuncAttributeMaxDynamicSharedMemorySize, DYN_SMEM_WV);
        attr_done = 1;
    }

    // [0] input hi/lo splits (p_features + v_features, one launch)
    splitall_kernel<<<(unsigned)((NP2 + NV2 + 255)/256), 256>>>(p_features, v_features);
    // [1] weight transpose+split (all three, one launch)
    wtsplitall_kernel<<<768, 256>>>(Wq, Wk, Wv);
    // [2] positional path
    pv_relu_kernel<<<R_/256, 256>>>(p_xyz, v_xyz, Wp1, bp1, ln_w, ln_b);
    // [3] fused projections q/k/v (128 threads, 64x64 warp tiles)
    proj_mma_kernel<<<dim3(2, R_/128, 3), 128, DYN_SMEM>>>(bq, bk, bv, Wp2, bp2);
    // [4] V transpose + split
    vtrans_kernel<<<dim3(N_/32, D_/32, B_), dim3(32, 8)>>>();
    // [5] logits + fused partial stats (128 threads, 64x64 warp tiles)
    logits_mma_kernel<<<dim3(N_/128, M_/128, B_), 128, DYN_SMEM>>>();
    // [6] stats reduce
    cstat_reduce_kernel<<<(B_*N_)/256, 256>>>();
    // [7] weighted value (2-pass, split-K=4 -> one clean wave)
    wv_mma_kernel<<<dim3(D_/128, M_/128, B_*NSPLIT), 256, DYN_SMEM_WV>>>();
    // [8] reduce + residual
    reduce_kernel<<<(RQ_*D_/4)/256, 256>>>(v_features, out);
}

// round 8
// speedup vs baseline: 1.1614x; 1.1614x over previous
#include <cuda_runtime.h>
#include <cuda_fp16.h>
#include <stdint.h>
#include <math.h>

#define B_  2
#define N_  16384
#define M_  2048
#define D_  256
#define R_  (B_*N_)
#define RQ_ (B_*M_)
#define NSPLIT 4
#define KR_ (N_/NSPLIT)          // 4096 contraction per wv split
#define NMT 16                   // number of m-tiles (M_/128)
#define STAGE_BYTES 32768        // proj: Ah(8K) Al(8K) Bh(8K) Bl(8K)
#define DYN_SMEM (3*STAGE_BYTES)
#define STAGE3 24576             // logits/wv: X(8K) Bh(8K) Bl(8K)
#define DYN_SMEM3 (3*STAGE3)

// ======================= device scratch =====================================
__device__ __align__(16) float  g_r[R_*3];
__device__ __align__(16) __half g_ph [(size_t)R_*D_],  g_pl [(size_t)R_*D_];
__device__ __align__(16) __half g_vfh[(size_t)RQ_*D_], g_vfl[(size_t)RQ_*D_];
__device__ __align__(16) __half g_wqTh[D_*D_], g_wqTl[D_*D_];
__device__ __align__(16) __half g_wkTh[D_*D_], g_wkTl[D_*D_];
__device__ __align__(16) __half g_wvTh[D_*D_], g_wvTl[D_*D_];
__device__ __align__(16) __half g_qh [(size_t)RQ_*D_];        // pre-scaled by 1/16
__device__ __align__(16) __half g_kpvh[(size_t)R_*D_], g_kpvl[(size_t)R_*D_];
__device__ __align__(16) float  g_v[(size_t)R_*D_];
__device__ __align__(16) __half g_vth[(size_t)B_*D_*N_], g_vtl[(size_t)B_*D_*N_];
__device__ __align__(16) float  g_logits[(size_t)B_*M_*N_];   // 256 MB (scaled)
__device__ __align__(16) float  g_pmax[NMT*B_*N_], g_psum[NMT*B_*N_];
__device__ __align__(16) float  g_cstat[B_*N_];
__device__ __align__(16) float  g_part[(size_t)B_*NSPLIT*M_*D_];

// ======================= small helpers ======================================
__device__ __forceinline__ uint32_t smem_u32(const void* p) {
    uint32_t a;
    asm("{ .reg .u64 t; cvta.to.shared.u64 t, %1; cvt.u32.u64 %0, t; }" : "=r"(a) : "l"(p));
    return a;
}
__device__ __forceinline__ void cp16(uint32_t dst, const void* src) {
    asm volatile("cp.async.cg.shared.global [%0], [%1], 16;" :: "r"(dst), "l"(src));
}
#define CP_COMMIT() asm volatile("cp.async.commit_group;" ::: "memory")
#define CP_WAIT0()  asm volatile("cp.async.wait_group 0;" ::: "memory")
#define CP_WAIT1()  asm volatile("cp.async.wait_group 1;" ::: "memory")

__device__ __forceinline__ void ldsm_x4(uint32_t& r0, uint32_t& r1, uint32_t& r2, uint32_t& r3,
                                        uint32_t addr) {
    asm volatile("ldmatrix.sync.aligned.m8n8.x4.shared.b16 {%0,%1,%2,%3}, [%4];"
                 : "=r"(r0), "=r"(r1), "=r"(r2), "=r"(r3) : "r"(addr));
}
__device__ __forceinline__ void mma16816(float* c, const uint32_t* a, uint32_t b0, uint32_t b1) {
    asm volatile(
        "mma.sync.aligned.m16n8k16.row.col.f32.f16.f16.f32 "
        "{%0,%1,%2,%3}, {%4,%5,%6,%7}, {%8,%9}, {%0,%1,%2,%3};"
        : "+f"(c[0]), "+f"(c[1]), "+f"(c[2]), "+f"(c[3])
        : "r"(a[0]), "r"(a[1]), "r"(a[2]), "r"(a[3]), "r"(b0), "r"(b1));
}

// swizzled byte offset in a 128-row x 32-half tile (64B rows)
__device__ __forceinline__ uint32_t sw(int row, int c16) {
    return (uint32_t)(row * 64 + ((c16 ^ ((row ^ (row >> 2)) & 3)) << 4));
}

// fast exp, FFMA-only (no MUFU). Valid for x <= 0 (args here are always <= 0).
__device__ __forceinline__ float fexp(float x) {
    x = fmaxf(x, -80.0f);
    float nf = fmaf(x, 1.4426950408889634f, 12582912.0f);
    int  i   = __float_as_int(nf) - 0x4B400000;
    float n  = nf - 12582912.0f;
    float f  = fmaf(n, -0.693145751953125f, x);
    f        = fmaf(n, -1.42860682030941723e-6f, f);
    float p = 1.3888889e-3f;
    p = fmaf(p, f, 8.3333333e-3f);
    p = fmaf(p, f, 4.1666668e-2f);
    p = fmaf(p, f, 1.6666667e-1f);
    p = fmaf(p, f, 5.0e-1f);
    p = fmaf(p, f, 1.0f);
    p = fmaf(p, f, 1.0f);
    return p * __int_as_float((i + 127) << 23);
}

// ======================= 3-pass MMA stage (proj), 64x32 warp tiles ===========
// stage layout: Ah @ +0, Al @ +8192, Bh @ +16384, Bl @ +24576
__device__ __forceinline__ void compute_stage(uint32_t sb, int mw0, int nw0,
                                              float cacc[4][4][4], int lane) {
    int arow = lane & 15, asel = lane >> 4;
    int brow = (lane & 7) + ((lane >> 4) << 3), bsel = (lane >> 3) & 1;
#pragma unroll
    for (int ks = 0; ks < 2; ks++) {
        uint32_t ah[4][4], bh[2][4];
#pragma unroll
        for (int mi = 0; mi < 4; mi++)
            ldsm_x4(ah[mi][0], ah[mi][1], ah[mi][2], ah[mi][3],
                    sb + sw(mw0 + mi*16 + arow, ks*2 + asel));
#pragma unroll
        for (int nb = 0; nb < 2; nb++)
            ldsm_x4(bh[nb][0], bh[nb][1], bh[nb][2], bh[nb][3],
                    sb + 16384 + sw(nw0 + nb*16 + brow, ks*2 + bsel));
#pragma unroll
        for (int mi = 0; mi < 4; mi++)
#pragma unroll
            for (int nj = 0; nj < 4; nj++)
                mma16816(cacc[mi][nj], ah[mi], bh[nj>>1][(nj&1)*2], bh[nj>>1][(nj&1)*2+1]);

        uint32_t bl[2][4];
#pragma unroll
        for (int nb = 0; nb < 2; nb++)
            ldsm_x4(bl[nb][0], bl[nb][1], bl[nb][2], bl[nb][3],
                    sb + 24576 + sw(nw0 + nb*16 + brow, ks*2 + bsel));
#pragma unroll
        for (int mi = 0; mi < 4; mi++)
#pragma unroll
            for (int nj = 0; nj < 4; nj++)
                mma16816(cacc[mi][nj], ah[mi], bl[nj>>1][(nj&1)*2], bl[nj>>1][(nj&1)*2+1]);

        uint32_t al[4][4];
#pragma unroll
        for (int mi = 0; mi < 4; mi++)
            ldsm_x4(al[mi][0], al[mi][1], al[mi][2], al[mi][3],
                    sb + 8192 + sw(mw0 + mi*16 + arow, ks*2 + asel));
#pragma unroll
        for (int mi = 0; mi < 4; mi++)
#pragma unroll
            for (int nj = 0; nj < 4; nj++)
                mma16816(cacc[mi][nj], al[mi], bh[nj>>1][(nj&1)*2], bh[nj>>1][(nj&1)*2+1]);
    }
}

// ======================= 2-pass MMA stage: X@0, Bh@8192, Bl@16384 ============
__device__ __forceinline__ void compute_stage2(uint32_t sb, int mw0, int nw0,
                                               float cacc[4][4][4], int lane) {
    int arow = lane & 15, asel = lane >> 4;
    int brow = (lane & 7) + ((lane >> 4) << 3), bsel = (lane >> 3) & 1;
#pragma unroll
    for (int ks = 0; ks < 2; ks++) {
        uint32_t ah[4][4], bh[2][4], bl[2][4];
#pragma unroll
        for (int mi = 0; mi < 4; mi++)
            ldsm_x4(ah[mi][0], ah[mi][1], ah[mi][2], ah[mi][3],
                    sb + sw(mw0 + mi*16 + arow, ks*2 + asel));
#pragma unroll
        for (int nb = 0; nb < 2; nb++)
            ldsm_x4(bh[nb][0], bh[nb][1], bh[nb][2], bh[nb][3],
                    sb + 8192 + sw(nw0 + nb*16 + brow, ks*2 + bsel));
#pragma unroll
        for (int mi = 0; mi < 4; mi++)
#pragma unroll
            for (int nj = 0; nj < 4; nj++)
                mma16816(cacc[mi][nj], ah[mi], bh[nj>>1][(nj&1)*2], bh[nj>>1][(nj&1)*2+1]);
#pragma unroll
        for (int nb = 0; nb < 2; nb++)
            ldsm_x4(bl[nb][0], bl[nb][1], bl[nb][2], bl[nb][3],
                    sb + 16384 + sw(nw0 + nb*16 + brow, ks*2 + bsel));
#pragma unroll
        for (int mi = 0; mi < 4; mi++)
#pragma unroll
            for (int nj = 0; nj < 4; nj++)
                mma16816(cacc[mi][nj], ah[mi], bl[nj>>1][(nj&1)*2], bl[nj>>1][(nj&1)*2+1]);
    }
}

// cp.async staging of a 3-pass proj stage (A hi/lo + B hi/lo), 256 threads
__device__ __forceinline__ void stage4(uint32_t sb,
                                       const __half* __restrict__ Ah, const __half* __restrict__ Al,
                                       size_t ar0, int lda,
                                       const __half* __restrict__ Bh, const __half* __restrict__ Bl,
                                       size_t br0, int ldb, int k0) {
    int t = threadIdx.x;
#pragma unroll
    for (int i = 0; i < 2; i++) {
        int c = t + 256*i;
        int row = c >> 2, c16 = c & 3;
        uint32_t so = sw(row, c16);
        size_t ka = (size_t)k0 + c16*8;
        cp16(sb + so,         Ah + (ar0 + row)*(size_t)lda + ka);
        cp16(sb + 8192 + so,  Al + (ar0 + row)*(size_t)lda + ka);
        cp16(sb + 16384 + so, Bh + (br0 + row)*(size_t)ldb + ka);
        cp16(sb + 24576 + so, Bl + (br0 + row)*(size_t)ldb + ka);
    }
}

// cp.async staging of a 2-pass stage (A hi + B hi/lo), 256 threads
__device__ __forceinline__ void stage3(uint32_t sb,
                                       const __half* __restrict__ Ah, size_t ar0,
                                       const __half* __restrict__ Bh, const __half* __restrict__ Bl,
                                       size_t br0, int k0) {
    int t = threadIdx.x;
#pragma unroll
    for (int i = 0; i < 2; i++) {
        int c = t + 256*i;
        int row = c >> 2, c16 = c & 3;
        uint32_t so = sw(row, c16);
        size_t ka = (size_t)k0 + c16*8;
        cp16(sb + so,         Ah + (ar0 + row)*(size_t)D_ + ka);
        cp16(sb + 8192 + so,  Bh + (br0 + row)*(size_t)D_ + ka);
        cp16(sb + 16384 + so, Bl + (br0 + row)*(size_t)D_ + ka);
    }
}

// ======================= K0: positional path ================================
__global__ void pv_relu_kernel(const float* __restrict__ p_xyz, const float* __restrict__ v_xyz,
                               const float* __restrict__ Wp1, const float* __restrict__ bp1,
                               const float* __restrict__ ln_w, const float* __restrict__ ln_b) {
    int idx = blockIdx.x * blockDim.x + threadIdx.x;
    if (idx >= R_) return;
    int b = idx / N_;
    float d0 = fabsf(p_xyz[idx*3+0] - v_xyz[b*3+0]);
    float d1 = fabsf(p_xyz[idx*3+1] - v_xyz[b*3+1]);
    float d2 = fabsf(p_xyz[idx*3+2] - v_xyz[b*3+2]);
    float h0 = d0*Wp1[0] + d1*Wp1[3] + d2*Wp1[6] + bp1[0];
    float h1 = d0*Wp1[1] + d1*Wp1[4] + d2*Wp1[7] + bp1[1];
    float h2 = d0*Wp1[2] + d1*Wp1[5] + d2*Wp1[8] + bp1[2];
    float mu = (h0 + h1 + h2) * (1.0f/3.0f);
    float e0 = h0-mu, e1 = h1-mu, e2 = h2-mu;
    float inv = rsqrtf((e0*e0 + e1*e1 + e2*e2) * (1.0f/3.0f) + 1e-5f);
    g_r[idx*3+0] = fmaxf(e0*inv*ln_w[0] + ln_b[0], 0.0f);
    g_r[idx*3+1] = fmaxf(e1*inv*ln_w[1] + ln_b[1], 0.0f);
    g_r[idx*3+2] = fmaxf(e2*inv*ln_w[2] + ln_b[2], 0.0f);
}

// ======================= prep: all hi/lo splits (one launch) =================
#define NP2 ((size_t)R_*D_/2)
#define NV2 ((size_t)RQ_*D_/2)
__global__ void splitall_kernel(const float* __restrict__ P, const float* __restrict__ VF) {
    size_t i = (size_t)blockIdx.x * blockDim.x + threadIdx.x;
    const float* src; __half *hi, *lo; size_t j;
    if (i < NP2)                 { src = P;  hi = g_ph;  lo = g_pl;  j = i; }
    else if (i < NP2 + NV2)      { src = VF; hi = g_vfh; lo = g_vfl; j = i - NP2; }
    else return;
    float2 v = reinterpret_cast<const float2*>(src)[j];
    __half h0 = __float2half_rn(v.x), h1 = __float2half_rn(v.y);
    __half l0 = __float2half_rn(v.x - __half2float(h0));
    __half l1 = __float2half_rn(v.y - __half2float(h1));
    reinterpret_cast<__half2*>(hi)[j] = __halves2half2(h0, h1);
    reinterpret_cast<__half2*>(lo)[j] = __halves2half2(l0, l1);
}

__global__ void wtsplitall_kernel(const float* __restrict__ Wq, const float* __restrict__ Wk,
                                  const float* __restrict__ Wv) {
    int i = blockIdx.x * blockDim.x + threadIdx.x;   // 3*65536
    int w = i >> 16, rem = i & 65535;
    int d = rem >> 8, c = rem & 255;
    const float* W = (w == 0) ? Wq : (w == 1) ? Wk : Wv;
    __half* Th = (w == 0) ? g_wqTh : (w == 1) ? g_wkTh : g_wvTh;
    __half* Tl = (w == 0) ? g_wqTl : (w == 1) ? g_wkTl : g_wvTl;
    float v = W[rem];
    __half h = __float2half_rn(v);
    Th[c*256 + d] = h;
    Tl[c*256 + d] = __float2half_rn(v - __half2float(h));
}

// ======================= fused projections (HMMA, one launch) ================
// z=0: q = (vf@Wq + bq)/16 -> qh ; z=1: kpv = p@Wk + bk + pv ; z=2: v (fp32)
__global__ __launch_bounds__(256, 2)
void proj_mma_kernel(const float* __restrict__ bq, const float* __restrict__ bk,
                     const float* __restrict__ bv, const float* __restrict__ Wp2,
                     const float* __restrict__ bp2) {
    int mode = blockIdx.z;
    if (mode == 0 && blockIdx.y >= RQ_/128) return;
    extern __shared__ char dyn[];
    uint32_t sb = smem_u32(dyn);
    const __half *Xh, *Xl, *WTh, *WTl; const float* bias;
    if (mode == 0)      { Xh = g_vfh; Xl = g_vfl; WTh = g_wqTh; WTl = g_wqTl; bias = bq; }
    else if (mode == 1) { Xh = g_ph;  Xl = g_pl;  WTh = g_wkTh; WTl = g_wkTl; bias = bk; }
    else                { Xh = g_ph;  Xl = g_pl;  WTh = g_wvTh; WTl = g_wvTl; bias = bv; }

    size_t row0 = (size_t)blockIdx.y * 128;
    int c0 = blockIdx.x * 128;
    int lane = threadIdx.x & 31, wid = threadIdx.x >> 5;
    int mw0 = (wid >> 2) * 64, nw0 = (wid & 3) * 32;
    float cacc[4][4][4] = {};

    stage4(sb + 0*STAGE_BYTES, Xh, Xl, row0, D_, WTh, WTl, (size_t)c0, D_, 0);  CP_COMMIT();
    stage4(sb + 1*STAGE_BYTES, Xh, Xl, row0, D_, WTh, WTl, (size_t)c0, D_, 32); CP_COMMIT();
#pragma unroll 1
    for (int s = 0; s < 8; s++) {
        if (s < 7) CP_WAIT1(); else CP_WAIT0();
        __syncthreads();
        if (s + 2 < 8) {
            stage4(sb + ((s+2)%3)*STAGE_BYTES, Xh, Xl, row0, D_, WTh, WTl, (size_t)c0, D_, (s+2)*32);
            CP_COMMIT();
        }
        compute_stage(sb + (s%3)*STAGE_BYTES, mw0, nw0, cacc, lane);
    }

    int g = lane >> 2, tg = lane & 3;
#pragma unroll
    for (int mi = 0; mi < 4; mi++) {
#pragma unroll
        for (int half_m = 0; half_m < 2; half_m++) {
            size_t r = row0 + mw0 + mi*16 + g + half_m*8;
            float q0 = 0.f, q1 = 0.f, q2 = 0.f;
            if (mode == 1) { q0 = g_r[r*3+0]; q1 = g_r[r*3+1]; q2 = g_r[r*3+2]; }
#pragma unroll
            for (int nj = 0; nj < 4; nj++) {
#pragma unroll
                for (int e = 0; e < 2; e++) {
                    int c = c0 + nw0 + nj*8 + tg*2 + e;
                    float v = cacc[mi][nj][half_m*2 + e] + bias[c];
                    if (mode == 1) v += q0*Wp2[c] + q1*Wp2[D_+c] + q2*Wp2[2*D_+c] + bp2[c];
                    if (mode == 2) { g_v[r*D_ + c] = v; }
                    else if (mode == 0) {
                        g_qh[r*D_+c] = __float2half_rn(v * 0.0625f);  // pre-scale
                    } else {
                        __half h = __float2half_rn(v);
                        __half l = __float2half_rn(v - __half2float(h));
                        g_kpvh[r*D_+c] = h; g_kpvl[r*D_+c] = l;
                    }
                }
            }
        }
    }
}

// ======================= V transpose + split =================================
__global__ void vtrans_kernel() {
    __shared__ float tl[32][33];
    int n0 = blockIdx.x * 32, d0 = blockIdx.y * 32, b = blockIdx.z;
    int tx = threadIdx.x, ty = threadIdx.y;
#pragma unroll
    for (int k = 0; k < 4; k++)
        tl[ty + k*8][tx] = g_v[(size_t)(b*N_ + n0 + ty + k*8)*D_ + d0 + tx];
    __syncthreads();
#pragma unroll
    for (int k = 0; k < 4; k++) {
        int d = d0 + ty + k*8;
        float v = tl[tx][ty + k*8];
        __half h = __float2half_rn(v);
        size_t o = (size_t)(b*D_ + d)*N_ + n0 + tx;
        g_vth[o] = h;
        g_vtl[o] = __float2half_rn(v - __half2float(h));
    }
}

// ======================= logits (HMMA 2-pass) + fused partial stats ==========
__global__ __launch_bounds__(256, 2)
void logits_mma_kernel() {
    extern __shared__ char dyn[];
    uint32_t sb = smem_u32(dyn);
    int b = blockIdx.z;
    int n0 = blockIdx.x * 128, m0 = blockIdx.y * 128;
    size_t ar0 = (size_t)b*M_ + m0, br0 = (size_t)b*N_ + n0;
    int lane = threadIdx.x & 31, wid = threadIdx.x >> 5;
    int mw0 = (wid >> 2) * 64, nw0 = (wid & 3) * 32;
    float cacc[4][4][4] = {};

    stage3(sb + 0*STAGE3, g_qh, ar0, g_kpvh, g_kpvl, br0, 0);  CP_COMMIT();
    stage3(sb + 1*STAGE3, g_qh, ar0, g_kpvh, g_kpvl, br0, 32); CP_COMMIT();
#pragma unroll 1
    for (int s = 0; s < 8; s++) {
        if (s < 7) CP_WAIT1(); else CP_WAIT0();
        __syncthreads();
        if (s + 2 < 8) {
            stage3(sb + ((s+2)%3)*STAGE3, g_qh, ar0, g_kpvh, g_kpvl, br0, (s+2)*32);
            CP_COMMIT();
        }
        compute_stage2(sb + (s%3)*STAGE3, mw0, nw0, cacc, lane);
    }

    int g = lane >> 2, tg = lane & 3;
    float* L = g_logits + (size_t)b*M_*N_;
#pragma unroll
    for (int mi = 0; mi < 4; mi++)
#pragma unroll
        for (int nj = 0; nj < 4; nj++) {
            int m = m0 + mw0 + mi*16 + g;
            int n = n0 + nw0 + nj*8 + tg*2;
            float2 v0 = { cacc[mi][nj][0], cacc[mi][nj][1] };
            float2 v1 = { cacc[mi][nj][2], cacc[mi][nj][3] };
            *reinterpret_cast<float2*>(&L[(size_t)m*N_ + n])     = v0;
            *reinterpret_cast<float2*>(&L[(size_t)(m+8)*N_ + n]) = v1;
        }

    // per-column (over 128 m rows of this tile) max + sumexp partials
    __syncthreads();              // smem (dyn) free for reuse now
    float* smax = reinterpret_cast<float*>(dyn);        // [2][128]
    float* ssum = smax + 256;                            // [2][128]
#pragma unroll
    for (int nj = 0; nj < 4; nj++) {
#pragma unroll
        for (int ec = 0; ec < 2; ec++) {
            float mx = -1e30f;
#pragma unroll
            for (int mi = 0; mi < 4; mi++) {
                mx = fmaxf(mx, cacc[mi][nj][ec]);
                mx = fmaxf(mx, cacc[mi][nj][2 + ec]);
            }
            mx = fmaxf(mx, __shfl_xor_sync(0xFFFFFFFFu, mx, 4));
            mx = fmaxf(mx, __shfl_xor_sync(0xFFFFFFFFu, mx, 8));
            mx = fmaxf(mx, __shfl_xor_sync(0xFFFFFFFFu, mx, 16));
            float s = 0.0f;
#pragma unroll
            for (int mi = 0; mi < 4; mi++) {
                s += fexp(cacc[mi][nj][ec]     - mx);
                s += fexp(cacc[mi][nj][2 + ec] - mx);
            }
            s += __shfl_xor_sync(0xFFFFFFFFu, s, 4);
            s += __shfl_xor_sync(0xFFFFFFFFu, s, 8);
            s += __shfl_xor_sync(0xFFFFFFFFu, s, 16);
            if (g == 0) {
                int nc = (wid & 3)*32 + nj*8 + tg*2 + ec;
                smax[(wid >> 2)*128 + nc] = mx;
                ssum[(wid >> 2)*128 + nc] = s;
            }
        }
    }
    __syncthreads();
    int t = threadIdx.x;
    if (t < 128) {
        float m0v = smax[t], m1v = smax[128 + t];
        float s0  = ssum[t], s1  = ssum[128 + t];
        float mm = fmaxf(m0v, m1v);
        float ss = s0 * fexp(m0v - mm) + s1 * fexp(m1v - mm);
        int col = b*N_ + n0 + t;
        g_pmax[blockIdx.y*(B_*N_) + col] = mm;
        g_psum[blockIdx.y*(B_*N_) + col] = ss;
    }
}

// ======================= stats reduce over m-tiles ===========================
__global__ void cstat_reduce_kernel() {
    int col = blockIdx.x * blockDim.x + threadIdx.x;   // 0..B*N-1
    float mx = -1e30f, sum = 0.0f;
#pragma unroll
    for (int ti = 0; ti < NMT; ti++) {
        float m2 = g_pmax[ti*(B_*N_) + col];
        float s2 = g_psum[ti*(B_*N_) + col];
        if (m2 > mx) { sum = sum * fexp(mx - m2) + s2; mx = m2; }
        else         { sum += s2 * fexp(m2 - mx); }
    }
    g_cstat[col] = mx + __logf(sum);
}

// ======================= weighted value (HMMA 2-pass, split-K, fused exp) ====
__global__ __launch_bounds__(256, 2)
void wv_mma_kernel() {
    extern __shared__ char dyn[];
    uint32_t sb = smem_u32(dyn);
    int z = blockIdx.z, b = z >> 2, sp = z & 3;
    int d0 = blockIdx.x * 128, m0 = blockIdx.y * 128;
    int kbeg = sp * KR_;
    const float* L  = g_logits + (size_t)b*M_*N_;
    const float* CS = g_cstat + b*N_;
    size_t br0 = (size_t)b*D_ + d0;
    int t = threadIdx.x, lane = t & 31, wid = t >> 5;
    int mw0 = (wid >> 2) * 64, nw0 = (wid & 3) * 32;
    float cacc[4][4][4] = {};

    int rows[2], c16s[2];
#pragma unroll
    for (int i = 0; i < 2; i++) { int c = t + 256*i; rows[i] = c >> 2; c16s[i] = c & 3; }

    float4 ra[2][2];
    // prologue: LDG A(0); cp.async B(0), B(1)
#pragma unroll
    for (int i = 0; i < 2; i++) {
        size_t base = (size_t)(m0 + rows[i])*N_ + kbeg + c16s[i]*8;
        ra[i][0] = *reinterpret_cast<const float4*>(&L[base]);
        ra[i][1] = *reinterpret_cast<const float4*>(&L[base + 4]);
    }
#pragma unroll
    for (int st = 0; st < 2; st++) {
        uint32_t bufB = sb + st*STAGE3;
#pragma unroll
        for (int i = 0; i < 2; i++) {
            uint32_t so = sw(rows[i], c16s[i]);
            size_t ka = (size_t)(kbeg + st*32) + c16s[i]*8;
            cp16(bufB + 8192  + so, g_vth + (br0 + rows[i])*(size_t)N_ + ka);
            cp16(bufB + 16384 + so, g_vtl + (br0 + rows[i])*(size_t)N_ + ka);
        }
        CP_COMMIT();
    }

    const int NCH = KR_ / 32;   // 128
#pragma unroll 1
    for (int s = 0; s < NCH; s++) {
        uint32_t buf  = sb + (s%3)*STAGE3;
        char*    bufp = dyn + (s%3)*STAGE3;
        if (s < NCH-1) CP_WAIT1(); else CP_WAIT0();
        // transform + STS A(s): weights hi only (2-pass drops w_lo)
#pragma unroll
        for (int i = 0; i < 2; i++) {
            int kabs = kbeg + s*32 + c16s[i]*8;
            float4 cs0 = *reinterpret_cast<const float4*>(&CS[kabs]);
            float4 cs1 = *reinterpret_cast<const float4*>(&CS[kabs + 4]);
            float w[8];
            w[0] = fexp(ra[i][0].x - cs0.x); w[1] = fexp(ra[i][0].y - cs0.y);
            w[2] = fexp(ra[i][0].z - cs0.z); w[3] = fexp(ra[i][0].w - cs0.w);
            w[4] = fexp(ra[i][1].x - cs1.x); w[5] = fexp(ra[i][1].y - cs1.y);
            w[6] = fexp(ra[i][1].z - cs1.z); w[7] = fexp(ra[i][1].w - cs1.w);
            uint32_t hi[4];
#pragma unroll
            for (int j = 0; j < 4; j++) {
                __half h0 = __float2half_rn(w[2*j]), h1 = __float2half_rn(w[2*j+1]);
                hi[j] = (uint32_t)__half_as_ushort(h0) | ((uint32_t)__half_as_ushort(h1) << 16);
            }
            uint32_t so = sw(rows[i], c16s[i]);
            *reinterpret_cast<uint4*>(bufp + so) = make_uint4(hi[0], hi[1], hi[2], hi[3]);
        }
        __syncthreads();
        if (s + 1 < NCH) {
            int kn = kbeg + (s+1)*32;
#pragma unroll
            for (int i = 0; i < 2; i++) {
                size_t base = (size_t)(m0 + rows[i])*N_ + kn + c16s[i]*8;
                ra[i][0] = *reinterpret_cast<const float4*>(&L[base]);
                ra[i][1] = *reinterpret_cast<const float4*>(&L[base + 4]);
            }
        }
        if (s + 2 < NCH) {
            uint32_t nbuf = sb + ((s+2)%3)*STAGE3;
            int kn2 = kbeg + (s+2)*32;
#pragma unroll
            for (int i = 0; i < 2; i++) {
                uint32_t so = sw(rows[i], c16s[i]);
                size_t ka = (size_t)kn2 + c16s[i]*8;
                cp16(nbuf + 8192  + so, g_vth + (br0 + rows[i])*(size_t)N_ + ka);
                cp16(nbuf + 16384 + so, g_vtl + (br0 + rows[i])*(size_t)N_ + ka);
            }
            CP_COMMIT();
        }
        compute_stage2(buf, mw0, nw0, cacc, lane);
    }

    int g = lane >> 2, tg = lane & 3;
    float* P = g_part + (size_t)z*M_*D_;
#pragma unroll
    for (int mi = 0; mi < 4; mi++)
#pragma unroll
        for (int nj = 0; nj < 4; nj++) {
            int m = m0 + mw0 + mi*16 + g;
            int d = d0 + nw0 + nj*8 + tg*2;
            float2 v0 = { cacc[mi][nj][0], cacc[mi][nj][1] };
            float2 v1 = { cacc[mi][nj][2], cacc[mi][nj][3] };
            *reinterpret_cast<float2*>(&P[(size_t)m*D_ + d])     = v0;
            *reinterpret_cast<float2*>(&P[(size_t)(m+8)*D_ + d]) = v1;
        }
}

// ======================= reduce + residual ===================================
__global__ void reduce_kernel(const float* __restrict__ Vf, float* __restrict__ out) {
    int i4 = blockIdx.x * blockDim.x + threadIdx.x;   // RQ_*D_/4
    int row = i4 >> 6;
    int b = row >> 11;
    int mrow = row & (M_ - 1);
    int d4 = i4 & 63;
    float4 acc = reinterpret_cast<const float4*>(Vf)[i4];
#pragma unroll
    for (int s = 0; s < NSPLIT; s++) {
        size_t pi = ((size_t)(b*NSPLIT + s)*M_ + mrow)*64 + d4;
        float4 p = reinterpret_cast<const float4*>(g_part)[pi];
        acc.x += p.x; acc.y += p.y; acc.z += p.z; acc.w += p.w;
    }
    reinterpret_cast<float4*>(out)[i4] = acc;
}

// ======================= launcher ============================================
extern "C" void kernel_launch(void* const* d_in, const int* in_sizes, int n_in,
                              void* d_out, int out_size) {
    const float* p_xyz      = (const float*)d_in[0];
    const float* v_xyz      = (const float*)d_in[1];
    const float* p_features = (const float*)d_in[2];
    const float* v_features = (const float*)d_in[3];
    const float* Wq  = (const float*)d_in[4];
    const float* bq  = (const float*)d_in[5];
    const float* Wk  = (const float*)d_in[6];
    const float* bk  = (const float*)d_in[7];
    const float* Wv  = (const float*)d_in[8];
    const float* bv  = (const float*)d_in[9];
    const float* Wp1 = (const float*)d_in[10];
    const float* bp1 = (const float*)d_in[11];
    const float* ln_w = (const float*)d_in[12];
    const float* ln_b = (const float*)d_in[13];
    const float* Wp2 = (const float*)d_in[14];
    const float* bp2 = (const float*)d_in[15];
    float* out = (float*)d_out;

    static int attr_done = 0;
    if (!attr_done) {
        cudaFuncSetAttribute(proj_mma_kernel,   cudaFuncAttributeMaxDynamicSharedMemorySize, DYN_SMEM);
        cudaFuncSetAttribute(logits_mma_kernel, cudaFuncAttributeMaxDynamicSharedMemorySize, DYN_SMEM3);
        cudaFuncSetAttribute(wv_mma_kernel,     cudaFuncAttributeMaxDynamicSharedMemorySize, DYN_SMEM3);
        attr_done = 1;
    }

    // [0] input hi/lo splits (p_features + v_features, one launch)
    splitall_kernel<<<(unsigned)((NP2 + NV2 + 255)/256), 256>>>(p_features, v_features);
    // [1] weight transpose+split (all three, one launch)
    wtsplitall_kernel<<<768, 256>>>(Wq, Wk, Wv);
    // [2] positional path
    pv_relu_kernel<<<R_/256, 256>>>(p_xyz, v_xyz, Wp1, bp1, ln_w, ln_b);
    // [3] fused projections q/k/v
    proj_mma_kernel<<<dim3(2, R_/128, 3), 256, DYN_SMEM>>>(bq, bk, bv, Wp2, bp2);
    // [4] V transpose + split
    vtrans_kernel<<<dim3(N_/32, D_/32, B_), dim3(32, 8)>>>();
    // [5] logits (2-pass) + fused partial stats
    logits_mma_kernel<<<dim3(N_/128, M_/128, B_), 256, DYN_SMEM3>>>();
    // [6] stats reduce
    cstat_reduce_kernel<<<(B_*N_)/256, 256>>>();
    // [7] weighted value (2-pass, split-K=4 -> one clean wave)
    wv_mma_kernel<<<dim3(D_/128, M_/128, B_*NSPLIT), 256, DYN_SMEM3>>>();
    // [8] reduce + residual
    reduce_kernel<<<(RQ_*D_/4)/256, 256>>>(v_features, out);
}

// round 9
// speedup vs baseline: 1.3873x; 1.1945x over previous
#include <cuda_runtime.h>
#include <cuda_fp16.h>
#include <stdint.h>
#include <math.h>

#define B_  2
#define N_  16384
#define M_  2048
#define D_  256
#define R_  (B_*N_)
#define RQ_ (B_*M_)
#define NSPLIT 4
#define KR_ (N_/NSPLIT)          // 4096 contraction per wv split
#define NMT 16                   // number of m-tiles (M_/128)
#define STAGE3 24576             // proj/logits: A(8K) Bh(8K) Bl(8K)
#define DYN_SMEM3 (3*STAGE3)
#define STAGE_WV 16384           // wv: A(8K) Vh(8K)
#define DYN_SMEM_WV (3*STAGE_WV)

// ======================= device scratch =====================================
__device__ __align__(16) float  g_r[R_*3];
__device__ __align__(16) __half g_ph [(size_t)R_*D_];
__device__ __align__(16) __half g_vfh[(size_t)RQ_*D_];
__device__ __align__(16) __half g_wqTh[D_*D_], g_wqTl[D_*D_];
__device__ __align__(16) __half g_wkTh[D_*D_], g_wkTl[D_*D_];
__device__ __align__(16) __half g_wvTh[D_*D_], g_wvTl[D_*D_];
__device__ __align__(16) __half g_qh [(size_t)RQ_*D_];        // pre-scaled by 1/16
__device__ __align__(16) __half g_kpvh[(size_t)R_*D_], g_kpvl[(size_t)R_*D_];
__device__ __align__(16) float  g_v[(size_t)R_*D_];
__device__ __align__(16) __half g_vth[(size_t)B_*D_*N_];
__device__ __align__(16) float  g_logits[(size_t)B_*M_*N_];   // 256 MB (scaled)
__device__ __align__(16) float  g_pmax[NMT*B_*N_], g_psum[NMT*B_*N_];
__device__ __align__(16) float  g_cstat[B_*N_];
__device__ __align__(16) float  g_part[(size_t)B_*NSPLIT*M_*D_];

// ======================= small helpers ======================================
__device__ __forceinline__ uint32_t smem_u32(const void* p) {
    uint32_t a;
    asm("{ .reg .u64 t; cvta.to.shared.u64 t, %1; cvt.u32.u64 %0, t; }" : "=r"(a) : "l"(p));
    return a;
}
__device__ __forceinline__ void cp16(uint32_t dst, const void* src) {
    asm volatile("cp.async.cg.shared.global [%0], [%1], 16;" :: "r"(dst), "l"(src));
}
#define CP_COMMIT() asm volatile("cp.async.commit_group;" ::: "memory")
#define CP_WAIT0()  asm volatile("cp.async.wait_group 0;" ::: "memory")
#define CP_WAIT1()  asm volatile("cp.async.wait_group 1;" ::: "memory")

__device__ __forceinline__ void ldsm_x4(uint32_t& r0, uint32_t& r1, uint32_t& r2, uint32_t& r3,
                                        uint32_t addr) {
    asm volatile("ldmatrix.sync.aligned.m8n8.x4.shared.b16 {%0,%1,%2,%3}, [%4];"
                 : "=r"(r0), "=r"(r1), "=r"(r2), "=r"(r3) : "r"(addr));
}
__device__ __forceinline__ void mma16816(float* c, const uint32_t* a, uint32_t b0, uint32_t b1) {
    asm volatile(
        "mma.sync.aligned.m16n8k16.row.col.f32.f16.f16.f32 "
        "{%0,%1,%2,%3}, {%4,%5,%6,%7}, {%8,%9}, {%0,%1,%2,%3};"
        : "+f"(c[0]), "+f"(c[1]), "+f"(c[2]), "+f"(c[3])
        : "r"(a[0]), "r"(a[1]), "r"(a[2]), "r"(a[3]), "r"(b0), "r"(b1));
}

// swizzled byte offset in a 128-row x 32-half tile (64B rows)
__device__ __forceinline__ uint32_t sw(int row, int c16) {
    return (uint32_t)(row * 64 + ((c16 ^ ((row ^ (row >> 2)) & 3)) << 4));
}

// fast exp, FFMA-only (no MUFU). Valid for x <= 0 (args here are always <= 0).
__device__ __forceinline__ float fexp(float x) {
    x = fmaxf(x, -80.0f);
    float nf = fmaf(x, 1.4426950408889634f, 12582912.0f);
    int  i   = __float_as_int(nf) - 0x4B400000;
    float n  = nf - 12582912.0f;
    float f  = fmaf(n, -0.693145751953125f, x);
    f        = fmaf(n, -1.42860682030941723e-6f, f);
    float p = 1.3888889e-3f;
    p = fmaf(p, f, 8.3333333e-3f);
    p = fmaf(p, f, 4.1666668e-2f);
    p = fmaf(p, f, 1.6666667e-1f);
    p = fmaf(p, f, 5.0e-1f);
    p = fmaf(p, f, 1.0f);
    p = fmaf(p, f, 1.0f);
    return p * __int_as_float((i + 127) << 23);
}

// ======================= 2-pass MMA stage: A@0, Bh@8192, Bl@16384 ============
__device__ __forceinline__ void compute_stage2(uint32_t sb, int mw0, int nw0,
                                               float cacc[4][4][4], int lane) {
    int arow = lane & 15, asel = lane >> 4;
    int brow = (lane & 7) + ((lane >> 4) << 3), bsel = (lane >> 3) & 1;
#pragma unroll
    for (int ks = 0; ks < 2; ks++) {
        uint32_t ah[4][4], bh[2][4], bl[2][4];
#pragma unroll
        for (int mi = 0; mi < 4; mi++)
            ldsm_x4(ah[mi][0], ah[mi][1], ah[mi][2], ah[mi][3],
                    sb + sw(mw0 + mi*16 + arow, ks*2 + asel));
#pragma unroll
        for (int nb = 0; nb < 2; nb++)
            ldsm_x4(bh[nb][0], bh[nb][1], bh[nb][2], bh[nb][3],
                    sb + 8192 + sw(nw0 + nb*16 + brow, ks*2 + bsel));
#pragma unroll
        for (int mi = 0; mi < 4; mi++)
#pragma unroll
            for (int nj = 0; nj < 4; nj++)
                mma16816(cacc[mi][nj], ah[mi], bh[nj>>1][(nj&1)*2], bh[nj>>1][(nj&1)*2+1]);
#pragma unroll
        for (int nb = 0; nb < 2; nb++)
            ldsm_x4(bl[nb][0], bl[nb][1], bl[nb][2], bl[nb][3],
                    sb + 16384 + sw(nw0 + nb*16 + brow, ks*2 + bsel));
#pragma unroll
        for (int mi = 0; mi < 4; mi++)
#pragma unroll
            for (int nj = 0; nj < 4; nj++)
                mma16816(cacc[mi][nj], ah[mi], bl[nj>>1][(nj&1)*2], bl[nj>>1][(nj&1)*2+1]);
    }
}

// ======================= 1-pass MMA stage (wv): A@0, Bh@8192 =================
__device__ __forceinline__ void compute_stage1(uint32_t sb, int mw0, int nw0,
                                               float cacc[4][4][4], int lane) {
    int arow = lane & 15, asel = lane >> 4;
    int brow = (lane & 7) + ((lane >> 4) << 3), bsel = (lane >> 3) & 1;
#pragma unroll
    for (int ks = 0; ks < 2; ks++) {
        uint32_t ah[4][4], bh[2][4];
#pragma unroll
        for (int mi = 0; mi < 4; mi++)
            ldsm_x4(ah[mi][0], ah[mi][1], ah[mi][2], ah[mi][3],
                    sb + sw(mw0 + mi*16 + arow, ks*2 + asel));
#pragma unroll
        for (int nb = 0; nb < 2; nb++)
            ldsm_x4(bh[nb][0], bh[nb][1], bh[nb][2], bh[nb][3],
                    sb + 8192 + sw(nw0 + nb*16 + brow, ks*2 + bsel));
#pragma unroll
        for (int mi = 0; mi < 4; mi++)
#pragma unroll
            for (int nj = 0; nj < 4; nj++)
                mma16816(cacc[mi][nj], ah[mi], bh[nj>>1][(nj&1)*2], bh[nj>>1][(nj&1)*2+1]);
    }
}

// cp.async staging of a 2-pass stage (A + B hi/lo), 256 threads, ld = D_
__device__ __forceinline__ void stage3(uint32_t sb,
                                       const __half* __restrict__ Ah, size_t ar0,
                                       const __half* __restrict__ Bh, const __half* __restrict__ Bl,
                                       size_t br0, int k0) {
    int t = threadIdx.x;
#pragma unroll
    for (int i = 0; i < 2; i++) {
        int c = t + 256*i;
        int row = c >> 2, c16 = c & 3;
        uint32_t so = sw(row, c16);
        size_t ka = (size_t)k0 + c16*8;
        cp16(sb + so,         Ah + (ar0 + row)*(size_t)D_ + ka);
        cp16(sb + 8192 + so,  Bh + (br0 + row)*(size_t)D_ + ka);
        cp16(sb + 16384 + so, Bl + (br0 + row)*(size_t)D_ + ka);
    }
}

// ======================= K0: positional path ================================
__global__ void pv_relu_kernel(const float* __restrict__ p_xyz, const float* __restrict__ v_xyz,
                               const float* __restrict__ Wp1, const float* __restrict__ bp1,
                               const float* __restrict__ ln_w, const float* __restrict__ ln_b) {
    int idx = blockIdx.x * blockDim.x + threadIdx.x;
    if (idx >= R_) return;
    int b = idx / N_;
    float d0 = fabsf(p_xyz[idx*3+0] - v_xyz[b*3+0]);
    float d1 = fabsf(p_xyz[idx*3+1] - v_xyz[b*3+1]);
    float d2 = fabsf(p_xyz[idx*3+2] - v_xyz[b*3+2]);
    float h0 = d0*Wp1[0] + d1*Wp1[3] + d2*Wp1[6] + bp1[0];
    float h1 = d0*Wp1[1] + d1*Wp1[4] + d2*Wp1[7] + bp1[1];
    float h2 = d0*Wp1[2] + d1*Wp1[5] + d2*Wp1[8] + bp1[2];
    float mu = (h0 + h1 + h2) * (1.0f/3.0f);
    float e0 = h0-mu, e1 = h1-mu, e2 = h2-mu;
    float inv = rsqrtf((e0*e0 + e1*e1 + e2*e2) * (1.0f/3.0f) + 1e-5f);
    g_r[idx*3+0] = fmaxf(e0*inv*ln_w[0] + ln_b[0], 0.0f);
    g_r[idx*3+1] = fmaxf(e1*inv*ln_w[1] + ln_b[1], 0.0f);
    g_r[idx*3+2] = fmaxf(e2*inv*ln_w[2] + ln_b[2], 0.0f);
}

// ======================= prep: fp16 converts (one launch) ====================
#define NP2 ((size_t)R_*D_/2)
#define NV2 ((size_t)RQ_*D_/2)
__global__ void cvt_kernel(const float* __restrict__ P, const float* __restrict__ VF) {
    size_t i = (size_t)blockIdx.x * blockDim.x + threadIdx.x;
    const float* src; __half* hi; size_t j;
    if (i < NP2)            { src = P;  hi = g_ph;  j = i; }
    else if (i < NP2 + NV2) { src = VF; hi = g_vfh; j = i - NP2; }
    else return;
    float2 v = reinterpret_cast<const float2*>(src)[j];
    reinterpret_cast<__half2*>(hi)[j] =
        __halves2half2(__float2half_rn(v.x), __float2half_rn(v.y));
}

__global__ void wtsplitall_kernel(const float* __restrict__ Wq, const float* __restrict__ Wk,
                                  const float* __restrict__ Wv) {
    int i = blockIdx.x * blockDim.x + threadIdx.x;   // 3*65536
    int w = i >> 16, rem = i & 65535;
    int d = rem >> 8, c = rem & 255;
    const float* W = (w == 0) ? Wq : (w == 1) ? Wk : Wv;
    __half* Th = (w == 0) ? g_wqTh : (w == 1) ? g_wkTh : g_wvTh;
    __half* Tl = (w == 0) ? g_wqTl : (w == 1) ? g_wkTl : g_wvTl;
    float v = W[rem];
    __half h = __float2half_rn(v);
    Th[c*256 + d] = h;
    Tl[c*256 + d] = __float2half_rn(v - __half2float(h));
}

// ======================= fused projections (HMMA 2-pass, one launch) =========
// z=0: q = (vf@Wq + bq)/16 -> qh ; z=1: kpv = p@Wk + bk + pv ; z=2: v (fp32)
__global__ __launch_bounds__(256, 2)
void proj_mma_kernel(const float* __restrict__ bq, const float* __restrict__ bk,
                     const float* __restrict__ bv, const float* __restrict__ Wp2,
                     const float* __restrict__ bp2) {
    int mode = blockIdx.z;
    if (mode == 0 && blockIdx.y >= RQ_/128) return;
    extern __shared__ char dyn[];
    uint32_t sb = smem_u32(dyn);
    const __half *Xh, *WTh, *WTl; const float* bias;
    if (mode == 0)      { Xh = g_vfh; WTh = g_wqTh; WTl = g_wqTl; bias = bq; }
    else if (mode == 1) { Xh = g_ph;  WTh = g_wkTh; WTl = g_wkTl; bias = bk; }
    else                { Xh = g_ph;  WTh = g_wvTh; WTl = g_wvTl; bias = bv; }

    size_t row0 = (size_t)blockIdx.y * 128;
    int c0 = blockIdx.x * 128;
    int lane = threadIdx.x & 31, wid = threadIdx.x >> 5;
    int mw0 = (wid >> 2) * 64, nw0 = (wid & 3) * 32;
    float cacc[4][4][4] = {};

    stage3(sb + 0*STAGE3, Xh, row0, WTh, WTl, (size_t)c0, 0);  CP_COMMIT();
    stage3(sb + 1*STAGE3, Xh, row0, WTh, WTl, (size_t)c0, 32); CP_COMMIT();
#pragma unroll 1
    for (int s = 0; s < 8; s++) {
        if (s < 7) CP_WAIT1(); else CP_WAIT0();
        __syncthreads();
        if (s + 2 < 8) {
            stage3(sb + ((s+2)%3)*STAGE3, Xh, row0, WTh, WTl, (size_t)c0, (s+2)*32);
            CP_COMMIT();
        }
        compute_stage2(sb + (s%3)*STAGE3, mw0, nw0, cacc, lane);
    }

    int g = lane >> 2, tg = lane & 3;
#pragma unroll
    for (int mi = 0; mi < 4; mi++) {
#pragma unroll
        for (int half_m = 0; half_m < 2; half_m++) {
            size_t r = row0 + mw0 + mi*16 + g + half_m*8;
            float q0 = 0.f, q1 = 0.f, q2 = 0.f;
            if (mode == 1) { q0 = g_r[r*3+0]; q1 = g_r[r*3+1]; q2 = g_r[r*3+2]; }
#pragma unroll
            for (int nj = 0; nj < 4; nj++) {
#pragma unroll
                for (int e = 0; e < 2; e++) {
                    int c = c0 + nw0 + nj*8 + tg*2 + e;
                    float v = cacc[mi][nj][half_m*2 + e] + bias[c];
                    if (mode == 1) v += q0*Wp2[c] + q1*Wp2[D_+c] + q2*Wp2[2*D_+c] + bp2[c];
                    if (mode == 2) { g_v[r*D_ + c] = v; }
                    else if (mode == 0) {
                        g_qh[r*D_+c] = __float2half_rn(v * 0.0625f);  // pre-scale
                    } else {
                        __half h = __float2half_rn(v);
                        __half l = __float2half_rn(v - __half2float(h));
                        g_kpvh[r*D_+c] = h; g_kpvl[r*D_+c] = l;
                    }
                }
            }
        }
    }
}

// ======================= V transpose (fp16 hi only) ==========================
__global__ void vtrans_kernel() {
    __shared__ float tl[32][33];
    int n0 = blockIdx.x * 32, d0 = blockIdx.y * 32, b = blockIdx.z;
    int tx = threadIdx.x, ty = threadIdx.y;
#pragma unroll
    for (int k = 0; k < 4; k++)
        tl[ty + k*8][tx] = g_v[(size_t)(b*N_ + n0 + ty + k*8)*D_ + d0 + tx];
    __syncthreads();
#pragma unroll
    for (int k = 0; k < 4; k++) {
        int d = d0 + ty + k*8;
        float v = tl[tx][ty + k*8];
        g_vth[(size_t)(b*D_ + d)*N_ + n0 + tx] = __float2half_rn(v);
    }
}

// ======================= logits (HMMA 2-pass) + fused partial stats ==========
__global__ __launch_bounds__(256, 2)
void logits_mma_kernel() {
    extern __shared__ char dyn[];
    uint32_t sb = smem_u32(dyn);
    int b = blockIdx.z;
    int n0 = blockIdx.x * 128, m0 = blockIdx.y * 128;
    size_t ar0 = (size_t)b*M_ + m0, br0 = (size_t)b*N_ + n0;
    int lane = threadIdx.x & 31, wid = threadIdx.x >> 5;
    int mw0 = (wid >> 2) * 64, nw0 = (wid & 3) * 32;
    float cacc[4][4][4] = {};

    stage3(sb + 0*STAGE3, g_qh, ar0, g_kpvh, g_kpvl, br0, 0);  CP_COMMIT();
    stage3(sb + 1*STAGE3, g_qh, ar0, g_kpvh, g_kpvl, br0, 32); CP_COMMIT();
#pragma unroll 1
    for (int s = 0; s < 8; s++) {
        if (s < 7) CP_WAIT1(); else CP_WAIT0();
        __syncthreads();
        if (s + 2 < 8) {
            stage3(sb + ((s+2)%3)*STAGE3, g_qh, ar0, g_kpvh, g_kpvl, br0, (s+2)*32);
            CP_COMMIT();
        }
        compute_stage2(sb + (s%3)*STAGE3, mw0, nw0, cacc, lane);
    }

    int g = lane >> 2, tg = lane & 3;
    float* L = g_logits + (size_t)b*M_*N_;
#pragma unroll
    for (int mi = 0; mi < 4; mi++)
#pragma unroll
        for (int nj = 0; nj < 4; nj++) {
            int m = m0 + mw0 + mi*16 + g;
            int n = n0 + nw0 + nj*8 + tg*2;
            float2 v0 = { cacc[mi][nj][0], cacc[mi][nj][1] };
            float2 v1 = { cacc[mi][nj][2], cacc[mi][nj][3] };
            *reinterpret_cast<float2*>(&L[(size_t)m*N_ + n])     = v0;
            *reinterpret_cast<float2*>(&L[(size_t)(m+8)*N_ + n]) = v1;
        }

    // per-column (over 128 m rows of this tile) max + sumexp partials
    __syncthreads();              // smem (dyn) free for reuse now
    float* smax = reinterpret_cast<float*>(dyn);        // [2][128]
    float* ssum = smax + 256;                            // [2][128]
#pragma unroll
    for (int nj = 0; nj < 4; nj++) {
#pragma unroll
        for (int ec = 0; ec < 2; ec++) {
            float mx = -1e30f;
#pragma unroll
            for (int mi = 0; mi < 4; mi++) {
                mx = fmaxf(mx, cacc[mi][nj][ec]);
                mx = fmaxf(mx, cacc[mi][nj][2 + ec]);
            }
            mx = fmaxf(mx, __shfl_xor_sync(0xFFFFFFFFu, mx, 4));
            mx = fmaxf(mx, __shfl_xor_sync(0xFFFFFFFFu, mx, 8));
            mx = fmaxf(mx, __shfl_xor_sync(0xFFFFFFFFu, mx, 16));
            float s = 0.0f;
#pragma unroll
            for (int mi = 0; mi < 4; mi++) {
                s += fexp(cacc[mi][nj][ec]     - mx);
                s += fexp(cacc[mi][nj][2 + ec] - mx);
            }
            s += __shfl_xor_sync(0xFFFFFFFFu, s, 4);
            s += __shfl_xor_sync(0xFFFFFFFFu, s, 8);
            s += __shfl_xor_sync(0xFFFFFFFFu, s, 16);
            if (g == 0) {
                int nc = (wid & 3)*32 + nj*8 + tg*2 + ec;
                smax[(wid >> 2)*128 + nc] = mx;
                ssum[(wid >> 2)*128 + nc] = s;
            }
        }
    }
    __syncthreads();
    int t = threadIdx.x;
    if (t < 128) {
        float m0v = smax[t], m1v = smax[128 + t];
        float s0  = ssum[t], s1  = ssum[128 + t];
        float mm = fmaxf(m0v, m1v);
        float ss = s0 * fexp(m0v - mm) + s1 * fexp(m1v - mm);
        int col = b*N_ + n0 + t;
        g_pmax[blockIdx.y*(B_*N_) + col] = mm;
        g_psum[blockIdx.y*(B_*N_) + col] = ss;
    }
}

// ======================= stats reduce over m-tiles ===========================
__global__ void cstat_reduce_kernel() {
    int col = blockIdx.x * blockDim.x + threadIdx.x;   // 0..B*N-1
    float mx = -1e30f, sum = 0.0f;
#pragma unroll
    for (int ti = 0; ti < NMT; ti++) {
        float m2 = g_pmax[ti*(B_*N_) + col];
        float s2 = g_psum[ti*(B_*N_) + col];
        if (m2 > mx) { sum = sum * fexp(mx - m2) + s2; mx = m2; }
        else         { sum += s2 * fexp(m2 - mx); }
    }
    g_cstat[col] = mx + __logf(sum);
}

// ======================= weighted value (HMMA 1-pass, split-K, fused exp) ====
__global__ __launch_bounds__(256, 2)
void wv_mma_kernel() {
    extern __shared__ char dyn[];
    uint32_t sb = smem_u32(dyn);
    int z = blockIdx.z, b = z >> 2, sp = z & 3;
    int d0 = blockIdx.x * 128, m0 = blockIdx.y * 128;
    int kbeg = sp * KR_;
    const float* L  = g_logits + (size_t)b*M_*N_;
    const float* CS = g_cstat + b*N_;
    size_t br0 = (size_t)b*D_ + d0;
    int t = threadIdx.x, lane = t & 31, wid = t >> 5;
    int mw0 = (wid >> 2) * 64, nw0 = (wid & 3) * 32;
    float cacc[4][4][4] = {};

    int rows[2], c16s[2];
#pragma unroll
    for (int i = 0; i < 2; i++) { int c = t + 256*i; rows[i] = c >> 2; c16s[i] = c & 3; }

    float4 ra[2][2];
    // prologue: LDG A(0); cp.async B(0), B(1)
#pragma unroll
    for (int i = 0; i < 2; i++) {
        size_t base = (size_t)(m0 + rows[i])*N_ + kbeg + c16s[i]*8;
        ra[i][0] = *reinterpret_cast<const float4*>(&L[base]);
        ra[i][1] = *reinterpret_cast<const float4*>(&L[base + 4]);
    }
#pragma unroll
    for (int st = 0; st < 2; st++) {
        uint32_t bufB = sb + st*STAGE_WV;
#pragma unroll
        for (int i = 0; i < 2; i++) {
            uint32_t so = sw(rows[i], c16s[i]);
            size_t ka = (size_t)(kbeg + st*32) + c16s[i]*8;
            cp16(bufB + 8192 + so, g_vth + (br0 + rows[i])*(size_t)N_ + ka);
        }
        CP_COMMIT();
    }

    const int NCH = KR_ / 32;   // 128
#pragma unroll 1
    for (int s = 0; s < NCH; s++) {
        uint32_t buf  = sb + (s%3)*STAGE_WV;
        char*    bufp = dyn + (s%3)*STAGE_WV;
        if (s < NCH-1) CP_WAIT1(); else CP_WAIT0();
        // transform + STS A(s): weights hi only
#pragma unroll
        for (int i = 0; i < 2; i++) {
            int kabs = kbeg + s*32 + c16s[i]*8;
            float4 cs0 = *reinterpret_cast<const float4*>(&CS[kabs]);
            float4 cs1 = *reinterpret_cast<const float4*>(&CS[kabs + 4]);
            float w[8];
            w[0] = fexp(ra[i][0].x - cs0.x); w[1] = fexp(ra[i][0].y - cs0.y);
            w[2] = fexp(ra[i][0].z - cs0.z); w[3] = fexp(ra[i][0].w - cs0.w);
            w[4] = fexp(ra[i][1].x - cs1.x); w[5] = fexp(ra[i][1].y - cs1.y);
            w[6] = fexp(ra[i][1].z - cs1.z); w[7] = fexp(ra[i][1].w - cs1.w);
            uint32_t hi[4];
#pragma unroll
            for (int j = 0; j < 4; j++) {
                __half h0 = __float2half_rn(w[2*j]), h1 = __float2half_rn(w[2*j+1]);
                hi[j] = (uint32_t)__half_as_ushort(h0) | ((uint32_t)__half_as_ushort(h1) << 16);
            }
            uint32_t so = sw(rows[i], c16s[i]);
            *reinterpret_cast<uint4*>(bufp + so) = make_uint4(hi[0], hi[1], hi[2], hi[3]);
        }
        __syncthreads();
        if (s + 1 < NCH) {
            int kn = kbeg + (s+1)*32;
#pragma unroll
            for (int i = 0; i < 2; i++) {
                size_t base = (size_t)(m0 + rows[i])*N_ + kn + c16s[i]*8;
                ra[i][0] = *reinterpret_cast<const float4*>(&L[base]);
                ra[i][1] = *reinterpret_cast<const float4*>(&L[base + 4]);
            }
        }
        if (s + 2 < NCH) {
            uint32_t nbuf = sb + ((s+2)%3)*STAGE_WV;
            int kn2 = kbeg + (s+2)*32;
#pragma unroll
            for (int i = 0; i < 2; i++) {
                uint32_t so = sw(rows[i], c16s[i]);
                size_t ka = (size_t)kn2 + c16s[i]*8;
                cp16(nbuf + 8192 + so, g_vth + (br0 + rows[i])*(size_t)N_ + ka);
            }
            CP_COMMIT();
        }
        compute_stage1(buf, mw0, nw0, cacc, lane);
    }

    int g = lane >> 2, tg = lane & 3;
    float* P = g_part + (size_t)z*M_*D_;
#pragma unroll
    for (int mi = 0; mi < 4; mi++)
#pragma unroll
        for (int nj = 0; nj < 4; nj++) {
            int m = m0 + mw0 + mi*16 + g;
            int d = d0 + nw0 + nj*8 + tg*2;
            float2 v0 = { cacc[mi][nj][0], cacc[mi][nj][1] };
            float2 v1 = { cacc[mi][nj][2], cacc[mi][nj][3] };
            *reinterpret_cast<float2*>(&P[(size_t)m*D_ + d])     = v0;
            *reinterpret_cast<float2*>(&P[(size_t)(m+8)*D_ + d]) = v1;
        }
}

// ======================= reduce + residual ===================================
__global__ void reduce_kernel(const float* __restrict__ Vf, float* __restrict__ out) {
    int i4 = blockIdx.x * blockDim.x + threadIdx.x;   // RQ_*D_/4
    int row = i4 >> 6;
    int b = row >> 11;
    int mrow = row & (M_ - 1);
    int d4 = i4 & 63;
    float4 acc = reinterpret_cast<const float4*>(Vf)[i4];
#pragma unroll
    for (int s = 0; s < NSPLIT; s++) {
        size_t pi = ((size_t)(b*NSPLIT + s)*M_ + mrow)*64 + d4;
        float4 p = reinterpret_cast<const float4*>(g_part)[pi];
        acc.x += p.x; acc.y += p.y; acc.z += p.z; acc.w += p.w;
    }
    reinterpret_cast<float4*>(out)[i4] = acc;
}

// ======================= launcher ============================================
extern "C" void kernel_launch(void* const* d_in, const int* in_sizes, int n_in,
                              void* d_out, int out_size) {
    const float* p_xyz      = (const float*)d_in[0];
    const float* v_xyz      = (const float*)d_in[1];
    const float* p_features = (const float*)d_in[2];
    const float* v_features = (const float*)d_in[3];
    const float* Wq  = (const float*)d_in[4];
    const float* bq  = (const float*)d_in[5];
    const float* Wk  = (const float*)d_in[6];
    const float* bk  = (const float*)d_in[7];
    const float* Wv  = (const float*)d_in[8];
    const float* bv  = (const float*)d_in[9];
    const float* Wp1 = (const float*)d_in[10];
    const float* bp1 = (const float*)d_in[11];
    const float* ln_w = (const float*)d_in[12];
    const float* ln_b = (const float*)d_in[13];
    const float* Wp2 = (const float*)d_in[14];
    const float* bp2 = (const float*)d_in[15];
    float* out = (float*)d_out;

    static int attr_done = 0;
    if (!attr_done) {
        cudaFuncSetAttribute(proj_mma_kernel,   cudaFuncAttributeMaxDynamicSharedMemorySize, DYN_SMEM3);
        cudaFuncSetAttribute(logits_mma_kernel, cudaFuncAttributeMaxDynamicSharedMemorySize, DYN_SMEM3);
        cudaFuncSetAttribute(wv_mma_kernel,     cudaFuncAttributeMaxDynamicSharedMemorySize, DYN_SMEM_WV);
        attr_done = 1;
    }

    // [0] fp16 converts (p_features + v_features)
    cvt_kernel<<<(unsigned)((NP2 + NV2 + 255)/256), 256>>>(p_features, v_features);
    // [1] weight transpose+split (all three, one launch)
    wtsplitall_kernel<<<768, 256>>>(Wq, Wk, Wv);
    // [2] positional path
    pv_relu_kernel<<<R_/256, 256>>>(p_xyz, v_xyz, Wp1, bp1, ln_w, ln_b);
    // [3] fused projections q/k/v (2-pass)
    proj_mma_kernel<<<dim3(2, R_/128, 3), 256, DYN_SMEM3>>>(bq, bk, bv, Wp2, bp2);
    // [4] V transpose (hi only)
    vtrans_kernel<<<dim3(N_/32, D_/32, B_), dim3(32, 8)>>>();
    // [5] logits (2-pass) + fused partial stats
    logits_mma_kernel<<<dim3(N_/128, M_/128, B_), 256, DYN_SMEM3>>>();
    // [6] stats reduce
    cstat_reduce_kernel<<<(B_*N_)/256, 256>>>();
    // [7] weighted value (1-pass, split-K=4 -> one clean wave)
    wv_mma_kernel<<<dim3(D_/128, M_/128, B_*NSPLIT), 256, DYN_SMEM_WV>>>();
    // [8] reduce + residual
    reduce_kernel<<<(RQ_*D_/4)/256, 256>>>(v_features, out);
}

// round 10
// speedup vs baseline: 1.8599x; 1.3406x over previous
#include <cuda_runtime.h>
#include <cuda_fp16.h>
#include <stdint.h>
#include <math.h>

#define B_  2
#define N_  16384
#define M_  2048
#define D_  256
#define R_  (B_*N_)
#define RQ_ (B_*M_)
#define NSPLIT 4
#define KR_ (N_/NSPLIT)          // 4096 contraction per wv split
#define NMT 16                   // number of m-tiles (M_/128)
#define STAGE3 24576             // proj: A(8K) Wh(8K) Wl(8K)
#define DYN_SMEM3 (3*STAGE3)
#define STAGE_L 16384            // logits: Q(8K) KPV(8K);  wv: W(8K) Vh(8K)
#define DYN_SMEM_L (3*STAGE_L)

// ======================= device scratch =====================================
__device__ __align__(16) float  g_r[R_*3];
__device__ __align__(16) __half g_ph [(size_t)R_*D_];
__device__ __align__(16) __half g_vfh[(size_t)RQ_*D_];
__device__ __align__(16) __half g_wqTh[D_*D_], g_wqTl[D_*D_];
__device__ __align__(16) __half g_wkTh[D_*D_], g_wkTl[D_*D_];
__device__ __align__(16) __half g_wvTh[D_*D_], g_wvTl[D_*D_];
__device__ __align__(16) __half g_qh [(size_t)RQ_*D_];        // pre-scaled by 1/16
__device__ __align__(16) __half g_kpvh[(size_t)R_*D_];
__device__ __align__(16) float  g_v[(size_t)R_*D_];
__device__ __align__(16) __half g_vth[(size_t)B_*D_*N_];
__device__ __align__(16) __half g_wexp[(size_t)B_*M_*N_];     // 128 MB: exp(l - m_tile)
__device__ __align__(16) __half g_sfact[NMT*B_*N_];           // exp(m_tile - cstat)
__device__ __align__(16) float  g_pmax[NMT*B_*N_], g_psum[NMT*B_*N_];
__device__ __align__(16) float  g_part[(size_t)B_*NSPLIT*M_*D_];

// ======================= small helpers ======================================
__device__ __forceinline__ uint32_t smem_u32(const void* p) {
    uint32_t a;
    asm("{ .reg .u64 t; cvta.to.shared.u64 t, %1; cvt.u32.u64 %0, t; }" : "=r"(a) : "l"(p));
    return a;
}
__device__ __forceinline__ void cp16(uint32_t dst, const void* src) {
    asm volatile("cp.async.cg.shared.global [%0], [%1], 16;" :: "r"(dst), "l"(src));
}
#define CP_COMMIT() asm volatile("cp.async.commit_group;" ::: "memory")
#define CP_WAIT0()  asm volatile("cp.async.wait_group 0;" ::: "memory")
#define CP_WAIT1()  asm volatile("cp.async.wait_group 1;" ::: "memory")

__device__ __forceinline__ void ldsm_x4(uint32_t& r0, uint32_t& r1, uint32_t& r2, uint32_t& r3,
                                        uint32_t addr) {
    asm volatile("ldmatrix.sync.aligned.m8n8.x4.shared.b16 {%0,%1,%2,%3}, [%4];"
                 : "=r"(r0), "=r"(r1), "=r"(r2), "=r"(r3) : "r"(addr));
}
__device__ __forceinline__ void mma16816(float* c, const uint32_t* a, uint32_t b0, uint32_t b1) {
    asm volatile(
        "mma.sync.aligned.m16n8k16.row.col.f32.f16.f16.f32 "
        "{%0,%1,%2,%3}, {%4,%5,%6,%7}, {%8,%9}, {%0,%1,%2,%3};"
        : "+f"(c[0]), "+f"(c[1]), "+f"(c[2]), "+f"(c[3])
        : "r"(a[0]), "r"(a[1]), "r"(a[2]), "r"(a[3]), "r"(b0), "r"(b1));
}

// swizzled byte offset in a 128-row x 32-half tile (64B rows)
__device__ __forceinline__ uint32_t sw(int row, int c16) {
    return (uint32_t)(row * 64 + ((c16 ^ ((row ^ (row >> 2)) & 3)) << 4));
}

// fast exp, FFMA-only (no MUFU). Valid for x <= 0 (args here are always <= 0).
__device__ __forceinline__ float fexp(float x) {
    x = fmaxf(x, -80.0f);
    float nf = fmaf(x, 1.4426950408889634f, 12582912.0f);
    int  i   = __float_as_int(nf) - 0x4B400000;
    float n  = nf - 12582912.0f;
    float f  = fmaf(n, -0.693145751953125f, x);
    f        = fmaf(n, -1.42860682030941723e-6f, f);
    float p = 1.3888889e-3f;
    p = fmaf(p, f, 8.3333333e-3f);
    p = fmaf(p, f, 4.1666668e-2f);
    p = fmaf(p, f, 1.6666667e-1f);
    p = fmaf(p, f, 5.0e-1f);
    p = fmaf(p, f, 1.0f);
    p = fmaf(p, f, 1.0f);
    return p * __int_as_float((i + 127) << 23);
}

// ======================= 2-pass MMA stage (proj): A@0, Bh@8192, Bl@16384 =====
__device__ __forceinline__ void compute_stage2(uint32_t sb, int mw0, int nw0,
                                               float cacc[4][4][4], int lane) {
    int arow = lane & 15, asel = lane >> 4;
    int brow = (lane & 7) + ((lane >> 4) << 3), bsel = (lane >> 3) & 1;
#pragma unroll
    for (int ks = 0; ks < 2; ks++) {
        uint32_t ah[4][4], bh[2][4], bl[2][4];
#pragma unroll
        for (int mi = 0; mi < 4; mi++)
            ldsm_x4(ah[mi][0], ah[mi][1], ah[mi][2], ah[mi][3],
                    sb + sw(mw0 + mi*16 + arow, ks*2 + asel));
#pragma unroll
        for (int nb = 0; nb < 2; nb++)
            ldsm_x4(bh[nb][0], bh[nb][1], bh[nb][2], bh[nb][3],
                    sb + 8192 + sw(nw0 + nb*16 + brow, ks*2 + bsel));
#pragma unroll
        for (int mi = 0; mi < 4; mi++)
#pragma unroll
            for (int nj = 0; nj < 4; nj++)
                mma16816(cacc[mi][nj], ah[mi], bh[nj>>1][(nj&1)*2], bh[nj>>1][(nj&1)*2+1]);
#pragma unroll
        for (int nb = 0; nb < 2; nb++)
            ldsm_x4(bl[nb][0], bl[nb][1], bl[nb][2], bl[nb][3],
                    sb + 16384 + sw(nw0 + nb*16 + brow, ks*2 + bsel));
#pragma unroll
        for (int mi = 0; mi < 4; mi++)
#pragma unroll
            for (int nj = 0; nj < 4; nj++)
                mma16816(cacc[mi][nj], ah[mi], bl[nj>>1][(nj&1)*2], bl[nj>>1][(nj&1)*2+1]);
    }
}

// ======================= 1-pass MMA stage: A@0, B@8192 =======================
__device__ __forceinline__ void compute_stage1(uint32_t sb, int mw0, int nw0,
                                               float cacc[4][4][4], int lane) {
    int arow = lane & 15, asel = lane >> 4;
    int brow = (lane & 7) + ((lane >> 4) << 3), bsel = (lane >> 3) & 1;
#pragma unroll
    for (int ks = 0; ks < 2; ks++) {
        uint32_t ah[4][4], bh[2][4];
#pragma unroll
        for (int mi = 0; mi < 4; mi++)
            ldsm_x4(ah[mi][0], ah[mi][1], ah[mi][2], ah[mi][3],
                    sb + sw(mw0 + mi*16 + arow, ks*2 + asel));
#pragma unroll
        for (int nb = 0; nb < 2; nb++)
            ldsm_x4(bh[nb][0], bh[nb][1], bh[nb][2], bh[nb][3],
                    sb + 8192 + sw(nw0 + nb*16 + brow, ks*2 + bsel));
#pragma unroll
        for (int mi = 0; mi < 4; mi++)
#pragma unroll
            for (int nj = 0; nj < 4; nj++)
                mma16816(cacc[mi][nj], ah[mi], bh[nj>>1][(nj&1)*2], bh[nj>>1][(nj&1)*2+1]);
    }
}

// cp.async staging, proj (A + W hi/lo), 256 threads, ld = D_
__device__ __forceinline__ void stage3(uint32_t sb,
                                       const __half* __restrict__ Ah, size_t ar0,
                                       const __half* __restrict__ Bh, const __half* __restrict__ Bl,
                                       size_t br0, int k0) {
    int t = threadIdx.x;
#pragma unroll
    for (int i = 0; i < 2; i++) {
        int c = t + 256*i;
        int row = c >> 2, c16 = c & 3;
        uint32_t so = sw(row, c16);
        size_t ka = (size_t)k0 + c16*8;
        cp16(sb + so,         Ah + (ar0 + row)*(size_t)D_ + ka);
        cp16(sb + 8192 + so,  Bh + (br0 + row)*(size_t)D_ + ka);
        cp16(sb + 16384 + so, Bl + (br0 + row)*(size_t)D_ + ka);
    }
}

// cp.async staging, logits (Q + KPV), 256 threads, ld = D_
__device__ __forceinline__ void stage2L(uint32_t sb,
                                        const __half* __restrict__ Ah, size_t ar0,
                                        const __half* __restrict__ Bh, size_t br0, int k0) {
    int t = threadIdx.x;
#pragma unroll
    for (int i = 0; i < 2; i++) {
        int c = t + 256*i;
        int row = c >> 2, c16 = c & 3;
        uint32_t so = sw(row, c16);
        size_t ka = (size_t)k0 + c16*8;
        cp16(sb + so,        Ah + (ar0 + row)*(size_t)D_ + ka);
        cp16(sb + 8192 + so, Bh + (br0 + row)*(size_t)D_ + ka);
    }
}

// ======================= K0: positional path ================================
__global__ void pv_relu_kernel(const float* __restrict__ p_xyz, const float* __restrict__ v_xyz,
                               const float* __restrict__ Wp1, const float* __restrict__ bp1,
                               const float* __restrict__ ln_w, const float* __restrict__ ln_b) {
    int idx = blockIdx.x * blockDim.x + threadIdx.x;
    if (idx >= R_) return;
    int b = idx / N_;
    float d0 = fabsf(p_xyz[idx*3+0] - v_xyz[b*3+0]);
    float d1 = fabsf(p_xyz[idx*3+1] - v_xyz[b*3+1]);
    float d2 = fabsf(p_xyz[idx*3+2] - v_xyz[b*3+2]);
    float h0 = d0*Wp1[0] + d1*Wp1[3] + d2*Wp1[6] + bp1[0];
    float h1 = d0*Wp1[1] + d1*Wp1[4] + d2*Wp1[7] + bp1[1];
    float h2 = d0*Wp1[2] + d1*Wp1[5] + d2*Wp1[8] + bp1[2];
    float mu = (h0 + h1 + h2) * (1.0f/3.0f);
    float e0 = h0-mu, e1 = h1-mu, e2 = h2-mu;
    float inv = rsqrtf((e0*e0 + e1*e1 + e2*e2) * (1.0f/3.0f) + 1e-5f);
    g_r[idx*3+0] = fmaxf(e0*inv*ln_w[0] + ln_b[0], 0.0f);
    g_r[idx*3+1] = fmaxf(e1*inv*ln_w[1] + ln_b[1], 0.0f);
    g_r[idx*3+2] = fmaxf(e2*inv*ln_w[2] + ln_b[2], 0.0f);
}

// ======================= prep: fp16 converts (one launch) ====================
#define NP2 ((size_t)R_*D_/2)
#define NV2 ((size_t)RQ_*D_/2)
__global__ void cvt_kernel(const float* __restrict__ P, const float* __restrict__ VF) {
    size_t i = (size_t)blockIdx.x * blockDim.x + threadIdx.x;
    const float* src; __half* hi; size_t j;
    if (i < NP2)            { src = P;  hi = g_ph;  j = i; }
    else if (i < NP2 + NV2) { src = VF; hi = g_vfh; j = i - NP2; }
    else return;
    float2 v = reinterpret_cast<const float2*>(src)[j];
    reinterpret_cast<__half2*>(hi)[j] =
        __halves2half2(__float2half_rn(v.x), __float2half_rn(v.y));
}

__global__ void wtsplitall_kernel(const float* __restrict__ Wq, const float* __restrict__ Wk,
                                  const float* __restrict__ Wv) {
    int i = blockIdx.x * blockDim.x + threadIdx.x;   // 3*65536
    int w = i >> 16, rem = i & 65535;
    int d = rem >> 8, c = rem & 255;
    const float* W = (w == 0) ? Wq : (w == 1) ? Wk : Wv;
    __half* Th = (w == 0) ? g_wqTh : (w == 1) ? g_wkTh : g_wvTh;
    __half* Tl = (w == 0) ? g_wqTl : (w == 1) ? g_wkTl : g_wvTl;
    float v = W[rem];
    __half h = __float2half_rn(v);
    Th[c*256 + d] = h;
    Tl[c*256 + d] = __float2half_rn(v - __half2float(h));
}

// ======================= fused projections (HMMA 2-pass, one launch) =========
// z=0: q = (vf@Wq + bq)/16 -> qh ; z=1: kpv = p@Wk + bk + pv ; z=2: v (fp32)
__global__ __launch_bounds__(256, 2)
void proj_mma_kernel(const float* __restrict__ bq, const float* __restrict__ bk,
                     const float* __restrict__ bv, const float* __restrict__ Wp2,
                     const float* __restrict__ bp2) {
    int mode = blockIdx.z;
    if (mode == 0 && blockIdx.y >= RQ_/128) return;
    extern __shared__ char dyn[];
    uint32_t sb = smem_u32(dyn);
    const __half *Xh, *WTh, *WTl; const float* bias;
    if (mode == 0)      { Xh = g_vfh; WTh = g_wqTh; WTl = g_wqTl; bias = bq; }
    else if (mode == 1) { Xh = g_ph;  WTh = g_wkTh; WTl = g_wkTl; bias = bk; }
    else                { Xh = g_ph;  WTh = g_wvTh; WTl = g_wvTl; bias = bv; }

    size_t row0 = (size_t)blockIdx.y * 128;
    int c0 = blockIdx.x * 128;
    int lane = threadIdx.x & 31, wid = threadIdx.x >> 5;
    int mw0 = (wid >> 2) * 64, nw0 = (wid & 3) * 32;
    float cacc[4][4][4] = {};

    stage3(sb + 0*STAGE3, Xh, row0, WTh, WTl, (size_t)c0, 0);  CP_COMMIT();
    stage3(sb + 1*STAGE3, Xh, row0, WTh, WTl, (size_t)c0, 32); CP_COMMIT();
#pragma unroll 1
    for (int s = 0; s < 8; s++) {
        if (s < 7) CP_WAIT1(); else CP_WAIT0();
        __syncthreads();
        if (s + 2 < 8) {
            stage3(sb + ((s+2)%3)*STAGE3, Xh, row0, WTh, WTl, (size_t)c0, (s+2)*32);
            CP_COMMIT();
        }
        compute_stage2(sb + (s%3)*STAGE3, mw0, nw0, cacc, lane);
    }

    int g = lane >> 2, tg = lane & 3;
#pragma unroll
    for (int mi = 0; mi < 4; mi++) {
#pragma unroll
        for (int half_m = 0; half_m < 2; half_m++) {
            size_t r = row0 + mw0 + mi*16 + g + half_m*8;
            float q0 = 0.f, q1 = 0.f, q2 = 0.f;
            if (mode == 1) { q0 = g_r[r*3+0]; q1 = g_r[r*3+1]; q2 = g_r[r*3+2]; }
#pragma unroll
            for (int nj = 0; nj < 4; nj++) {
#pragma unroll
                for (int e = 0; e < 2; e++) {
                    int c = c0 + nw0 + nj*8 + tg*2 + e;
                    float v = cacc[mi][nj][half_m*2 + e] + bias[c];
                    if (mode == 1) v += q0*Wp2[c] + q1*Wp2[D_+c] + q2*Wp2[2*D_+c] + bp2[c];
                    if (mode == 2)      { g_v[r*D_ + c] = v; }
                    else if (mode == 0) { g_qh[r*D_+c] = __float2half_rn(v * 0.0625f); }
                    else                { g_kpvh[r*D_+c] = __float2half_rn(v); }
                }
            }
        }
    }
}

// ======================= V transpose (fp16) ==================================
__global__ void vtrans_kernel() {
    __shared__ float tl[32][33];
    int n0 = blockIdx.x * 32, d0 = blockIdx.y * 32, b = blockIdx.z;
    int tx = threadIdx.x, ty = threadIdx.y;
#pragma unroll
    for (int k = 0; k < 4; k++)
        tl[ty + k*8][tx] = g_v[(size_t)(b*N_ + n0 + ty + k*8)*D_ + d0 + tx];
    __syncthreads();
#pragma unroll
    for (int k = 0; k < 4; k++) {
        int d = d0 + ty + k*8;
        float v = tl[tx][ty + k*8];
        g_vth[(size_t)(b*D_ + d)*N_ + n0 + tx] = __float2half_rn(v);
    }
}

// ======================= logits (HMMA 1-pass) -> fp16 tile-exp weights =======
__global__ __launch_bounds__(256, 2)
void logits_mma_kernel() {
    extern __shared__ char dyn[];
    uint32_t sb = smem_u32(dyn);
    int b = blockIdx.z;
    int n0 = blockIdx.x * 128, m0 = blockIdx.y * 128;
    size_t ar0 = (size_t)b*M_ + m0, br0 = (size_t)b*N_ + n0;
    int lane = threadIdx.x & 31, wid = threadIdx.x >> 5;
    int mw0 = (wid >> 2) * 64, nw0 = (wid & 3) * 32;
    float cacc[4][4][4] = {};

    stage2L(sb + 0*STAGE_L, g_qh, ar0, g_kpvh, br0, 0);  CP_COMMIT();
    stage2L(sb + 1*STAGE_L, g_qh, ar0, g_kpvh, br0, 32); CP_COMMIT();
#pragma unroll 1
    for (int s = 0; s < 8; s++) {
        if (s < 7) CP_WAIT1(); else CP_WAIT0();
        __syncthreads();
        if (s + 2 < 8) {
            stage2L(sb + ((s+2)%3)*STAGE_L, g_qh, ar0, g_kpvh, br0, (s+2)*32);
            CP_COMMIT();
        }
        compute_stage1(sb + (s%3)*STAGE_L, mw0, nw0, cacc, lane);
    }

    int g = lane >> 2, tg = lane & 3;
    float* smax = reinterpret_cast<float*>(dyn);        // [2][128]
    float* ssum = smax + 256;                            // [2][128]
    __syncthreads();   // mainloop smem reads done; reuse dyn

    // phase 1: per-warp (64-row) column maxes
#pragma unroll
    for (int nj = 0; nj < 4; nj++) {
#pragma unroll
        for (int ec = 0; ec < 2; ec++) {
            float mx = -1e30f;
#pragma unroll
            for (int mi = 0; mi < 4; mi++) {
                mx = fmaxf(mx, cacc[mi][nj][ec]);
                mx = fmaxf(mx, cacc[mi][nj][2 + ec]);
            }
            mx = fmaxf(mx, __shfl_xor_sync(0xFFFFFFFFu, mx, 4));
            mx = fmaxf(mx, __shfl_xor_sync(0xFFFFFFFFu, mx, 8));
            mx = fmaxf(mx, __shfl_xor_sync(0xFFFFFFFFu, mx, 16));
            if (g == 0) {
                int nc = (wid & 3)*32 + nj*8 + tg*2 + ec;
                smax[(wid >> 2)*128 + nc] = mx;
            }
        }
    }
    __syncthreads();

    // phase 2: w = exp(l - tile_col_max), store fp16, accumulate sums
    __half* W = g_wexp + (size_t)b*M_*N_;
#pragma unroll
    for (int nj = 0; nj < 4; nj++) {
        int ncb = (wid & 3)*32 + nj*8 + tg*2;
        float mx0 = fmaxf(smax[ncb],     smax[128 + ncb]);
        float mx1 = fmaxf(smax[ncb + 1], smax[128 + ncb + 1]);
        float s0 = 0.0f, s1 = 0.0f;
#pragma unroll
        for (int mi = 0; mi < 4; mi++) {
#pragma unroll
            for (int hm = 0; hm < 2; hm++) {
                float w0 = fexp(cacc[mi][nj][hm*2 + 0] - mx0);
                float w1 = fexp(cacc[mi][nj][hm*2 + 1] - mx1);
                s0 += w0; s1 += w1;
                int m = m0 + mw0 + mi*16 + g + hm*8;
                *reinterpret_cast<__half2*>(&W[(size_t)m*N_ + n0 + ncb]) =
                    __halves2half2(__float2half_rn(w0), __float2half_rn(w1));
            }
        }
        s0 += __shfl_xor_sync(0xFFFFFFFFu, s0, 4);
        s0 += __shfl_xor_sync(0xFFFFFFFFu, s0, 8);
        s0 += __shfl_xor_sync(0xFFFFFFFFu, s0, 16);
        s1 += __shfl_xor_sync(0xFFFFFFFFu, s1, 4);
        s1 += __shfl_xor_sync(0xFFFFFFFFu, s1, 8);
        s1 += __shfl_xor_sync(0xFFFFFFFFu, s1, 16);
        if (g == 0) {
            ssum[(wid >> 2)*128 + ncb]     = s0;
            ssum[(wid >> 2)*128 + ncb + 1] = s1;
        }
    }
    __syncthreads();
    int t = threadIdx.x;
    if (t < 128) {
        int col = b*N_ + n0 + t;
        g_pmax[blockIdx.y*(B_*N_) + col] = fmaxf(smax[t], smax[128 + t]);
        g_psum[blockIdx.y*(B_*N_) + col] = ssum[t] + ssum[128 + t];
    }
}

// ======================= stats reduce -> per-tile scale factors ==============
__global__ void cstat_reduce_kernel() {
    int col = blockIdx.x * blockDim.x + threadIdx.x;   // 0..B*N-1
    float pm[NMT];
    float mx = -1e30f, sum = 0.0f;
#pragma unroll
    for (int ti = 0; ti < NMT; ti++) {
        float m2 = g_pmax[ti*(B_*N_) + col];
        float s2 = g_psum[ti*(B_*N_) + col];
        pm[ti] = m2;
        if (m2 > mx) { sum = sum * fexp(mx - m2) + s2; mx = m2; }
        else         { sum += s2 * fexp(m2 - mx); }
    }
    float cs = mx + __logf(sum);
#pragma unroll
    for (int ti = 0; ti < NMT; ti++)
        g_sfact[ti*(B_*N_) + col] = __float2half_rn(fexp(pm[ti] - cs));
}

// ======================= weighted value (HMMA 1-pass, fp16 weights) ==========
__global__ __launch_bounds__(256, 2)
void wv_mma_kernel() {
    extern __shared__ char dyn[];
    uint32_t sb = smem_u32(dyn);
    int z = blockIdx.z, b = z >> 2, sp = z & 3;
    int d0 = blockIdx.x * 128, m0 = blockIdx.y * 128;
    int kbeg = sp * KR_;
    const __half* Wx = g_wexp + (size_t)b*M_*N_;
    const __half* SF = g_sfact + ((size_t)blockIdx.y*B_ + b)*N_;
    size_t br0 = (size_t)b*D_ + d0;
    int t = threadIdx.x, lane = t & 31, wid = t >> 5;
    int mw0 = (wid >> 2) * 64, nw0 = (wid & 3) * 32;
    float cacc[4][4][4] = {};

    int rows[2], c16s[2];
#pragma unroll
    for (int i = 0; i < 2; i++) { int c = t + 256*i; rows[i] = c >> 2; c16s[i] = c & 3; }

    uint4 wraw[2];
    // prologue: LDG W(0); cp.async V(0), V(1)
#pragma unroll
    for (int i = 0; i < 2; i++)
        wraw[i] = *reinterpret_cast<const uint4*>(
            Wx + (size_t)(m0 + rows[i])*N_ + kbeg + c16s[i]*8);
#pragma unroll
    for (int st = 0; st < 2; st++) {
        uint32_t bufB = sb + st*STAGE_L;
#pragma unroll
        for (int i = 0; i < 2; i++) {
            uint32_t so = sw(rows[i], c16s[i]);
            size_t ka = (size_t)(kbeg + st*32) + c16s[i]*8;
            cp16(bufB + 8192 + so, g_vth + (br0 + rows[i])*(size_t)N_ + ka);
        }
        CP_COMMIT();
    }

    const int NCH = KR_ / 32;   // 128
#pragma unroll 1
    for (int s = 0; s < NCH; s++) {
        uint32_t buf  = sb + (s%3)*STAGE_L;
        char*    bufp = dyn + (s%3)*STAGE_L;
        if (s < NCH-1) CP_WAIT1(); else CP_WAIT0();
        // transform + STS A(s): w = w_tile * sfact (half2 muls, no exp)
#pragma unroll
        for (int i = 0; i < 2; i++) {
            int kabs = kbeg + s*32 + c16s[i]*8;
            uint4 sf4 = *reinterpret_cast<const uint4*>(SF + kabs);
            const __half2* wp = reinterpret_cast<const __half2*>(&wraw[i]);
            const __half2* sp = reinterpret_cast<const __half2*>(&sf4);
            uint4 outv;
            __half2* op = reinterpret_cast<__half2*>(&outv);
            op[0] = __hmul2(wp[0], sp[0]);
            op[1] = __hmul2(wp[1], sp[1]);
            op[2] = __hmul2(wp[2], sp[2]);
            op[3] = __hmul2(wp[3], sp[3]);
            uint32_t so = sw(rows[i], c16s[i]);
            *reinterpret_cast<uint4*>(bufp + so) = outv;
        }
        __syncthreads();
        if (s + 1 < NCH) {
            int kn = kbeg + (s+1)*32;
#pragma unroll
            for (int i = 0; i < 2; i++)
                wraw[i] = *reinterpret_cast<const uint4*>(
                    Wx + (size_t)(m0 + rows[i])*N_ + kn + c16s[i]*8);
        }
        if (s + 2 < NCH) {
            uint32_t nbuf = sb + ((s+2)%3)*STAGE_L;
            int kn2 = kbeg + (s+2)*32;
#pragma unroll
            for (int i = 0; i < 2; i++) {
                uint32_t so = sw(rows[i], c16s[i]);
                size_t ka = (size_t)kn2 + c16s[i]*8;
                cp16(nbuf + 8192 + so, g_vth + (br0 + rows[i])*(size_t)N_ + ka);
            }
            CP_COMMIT();
        }
        compute_stage1(buf, mw0, nw0, cacc, lane);
    }

    int g = lane >> 2, tg = lane & 3;
    float* P = g_part + (size_t)z*M_*D_;
#pragma unroll
    for (int mi = 0; mi < 4; mi++)
#pragma unroll
        for (int nj = 0; nj < 4; nj++) {
            int m = m0 + mw0 + mi*16 + g;
            int d = d0 + nw0 + nj*8 + tg*2;
            float2 v0 = { cacc[mi][nj][0], cacc[mi][nj][1] };
            float2 v1 = { cacc[mi][nj][2], cacc[mi][nj][3] };
            *reinterpret_cast<float2*>(&P[(size_t)m*D_ + d])     = v0;
            *reinterpret_cast<float2*>(&P[(size_t)(m+8)*D_ + d]) = v1;
        }
}

// ======================= reduce + residual ===================================
__global__ void reduce_kernel(const float* __restrict__ Vf, float* __restrict__ out) {
    int i4 = blockIdx.x * blockDim.x + threadIdx.x;   // RQ_*D_/4
    int row = i4 >> 6;
    int b = row >> 11;
    int mrow = row & (M_ - 1);
    int d4 = i4 & 63;
    float4 acc = reinterpret_cast<const float4*>(Vf)[i4];
#pragma unroll
    for (int s = 0; s < NSPLIT; s++) {
        size_t pi = ((size_t)(b*NSPLIT + s)*M_ + mrow)*64 + d4;
        float4 p = reinterpret_cast<const float4*>(g_part)[pi];
        acc.x += p.x; acc.y += p.y; acc.z += p.z; acc.w += p.w;
    }
    reinterpret_cast<float4*>(out)[i4] = acc;
}

// ======================= launcher ============================================
extern "C" void kernel_launch(void* const* d_in, const int* in_sizes, int n_in,
                              void* d_out, int out_size) {
    const float* p_xyz      = (const float*)d_in[0];
    const float* v_xyz      = (const float*)d_in[1];
    const float* p_features = (const float*)d_in[2];
    const float* v_features = (const float*)d_in[3];
    const float* Wq  = (const float*)d_in[4];
    const float* bq  = (const float*)d_in[5];
    const float* Wk  = (const float*)d_in[6];
    const float* bk  = (const float*)d_in[7];
    const float* Wv  = (const float*)d_in[8];
    const float* bv  = (const float*)d_in[9];
    const float* Wp1 = (const float*)d_in[10];
    const float* bp1 = (const float*)d_in[11];
    const float* ln_w = (const float*)d_in[12];
    const float* ln_b = (const float*)d_in[13];
    const float* Wp2 = (const float*)d_in[14];
    const float* bp2 = (const float*)d_in[15];
    float* out = (float*)d_out;

    static int attr_done = 0;
    if (!attr_done) {
        cudaFuncSetAttribute(proj_mma_kernel,   cudaFuncAttributeMaxDynamicSharedMemorySize, DYN_SMEM3);
        cudaFuncSetAttribute(logits_mma_kernel, cudaFuncAttributeMaxDynamicSharedMemorySize, DYN_SMEM_L);
        cudaFuncSetAttribute(wv_mma_kernel,     cudaFuncAttributeMaxDynamicSharedMemorySize, DYN_SMEM_L);
        attr_done = 1;
    }

    // [0] fp16 converts (p_features + v_features)
    cvt_kernel<<<(unsigned)((NP2 + NV2 + 255)/256), 256>>>(p_features, v_features);
    // [1] weight transpose+split (all three, one launch)
    wtsplitall_kernel<<<768, 256>>>(Wq, Wk, Wv);
    // [2] positional path
    pv_relu_kernel<<<R_/256, 256>>>(p_xyz, v_xyz, Wp1, bp1, ln_w, ln_b);
    // [3] fused projections q/k/v (2-pass)
    proj_mma_kernel<<<dim3(2, R_/128, 3), 256, DYN_SMEM3>>>(bq, bk, bv, Wp2, bp2);
    // [4] V transpose
    vtrans_kernel<<<dim3(N_/32, D_/32, B_), dim3(32, 8)>>>();
    // [5] logits (1-pass) -> fp16 tile-exp weights + partial stats
    logits_mma_kernel<<<dim3(N_/128, M_/128, B_), 256, DYN_SMEM_L>>>();
    // [6] stats reduce -> per-tile fp16 scale factors
    cstat_reduce_kernel<<<(B_*N_)/256, 256>>>();
    // [7] weighted value (1-pass, fp16 weights * sfact, split-K=4)
    wv_mma_kernel<<<dim3(D_/128, M_/128, B_*NSPLIT), 256, DYN_SMEM_L>>>();
    // [8] reduce + residual
    reduce_kernel<<<(RQ_*D_/4)/256, 256>>>(v_features, out);
}

// round 11
// speedup vs baseline: 2.0495x; 1.1020x over previous
#include <cuda_runtime.h>
#include <cuda_fp16.h>
#include <stdint.h>
#include <math.h>

#define B_  2
#define N_  16384
#define M_  2048
#define D_  256
#define R_  (B_*N_)
#define RQ_ (B_*M_)
#define NSPLIT 4
#define KR_ (N_/NSPLIT)          // 4096 contraction per wv split
#define NMT 16                   // number of m-tiles (M_/128)
#define STAGE_L 16384            // all GEMMs: A(8K) B(8K)
#define DYN_SMEM_L (3*STAGE_L)   // 48 KB (also holds 128x132 fp16 transpose tile)

// ======================= device scratch =====================================
__device__ __align__(16) float  g_r[R_*3];
__device__ __align__(16) __half g_ph [(size_t)R_*D_];
__device__ __align__(16) __half g_vfh[(size_t)RQ_*D_];
__device__ __align__(16) __half g_wqT[D_*D_], g_wkT[D_*D_], g_wvT[D_*D_];
__device__ __align__(16) __half g_qh [(size_t)RQ_*D_];        // pre-scaled by 1/16
__device__ __align__(16) __half g_kpvh[(size_t)R_*D_];
__device__ __align__(16) __half g_vth[(size_t)B_*D_*N_];
__device__ __align__(16) __half g_wexp[(size_t)B_*M_*N_];     // 128 MB: exp(l - m_tile)
__device__ __align__(16) __half g_sfact[NMT*B_*N_];           // exp(m_tile - cstat)
__device__ __align__(16) float  g_pmax[NMT*B_*N_], g_psum[NMT*B_*N_];
__device__ __align__(16) float  g_part[(size_t)B_*NSPLIT*M_*D_];

// ======================= small helpers ======================================
__device__ __forceinline__ uint32_t smem_u32(const void* p) {
    uint32_t a;
    asm("{ .reg .u64 t; cvta.to.shared.u64 t, %1; cvt.u32.u64 %0, t; }" : "=r"(a) : "l"(p));
    return a;
}
__device__ __forceinline__ void cp16(uint32_t dst, const void* src) {
    asm volatile("cp.async.cg.shared.global [%0], [%1], 16;" :: "r"(dst), "l"(src));
}
#define CP_COMMIT() asm volatile("cp.async.commit_group;" ::: "memory")
#define CP_WAIT0()  asm volatile("cp.async.wait_group 0;" ::: "memory")
#define CP_WAIT1()  asm volatile("cp.async.wait_group 1;" ::: "memory")

__device__ __forceinline__ void ldsm_x4(uint32_t& r0, uint32_t& r1, uint32_t& r2, uint32_t& r3,
                                        uint32_t addr) {
    asm volatile("ldmatrix.sync.aligned.m8n8.x4.shared.b16 {%0,%1,%2,%3}, [%4];"
                 : "=r"(r0), "=r"(r1), "=r"(r2), "=r"(r3) : "r"(addr));
}
__device__ __forceinline__ void mma16816(float* c, const uint32_t* a, uint32_t b0, uint32_t b1) {
    asm volatile(
        "mma.sync.aligned.m16n8k16.row.col.f32.f16.f16.f32 "
        "{%0,%1,%2,%3}, {%4,%5,%6,%7}, {%8,%9}, {%0,%1,%2,%3};"
        : "+f"(c[0]), "+f"(c[1]), "+f"(c[2]), "+f"(c[3])
        : "r"(a[0]), "r"(a[1]), "r"(a[2]), "r"(a[3]), "r"(b0), "r"(b1));
}

// swizzled byte offset in a 128-row x 32-half tile (64B rows)
__device__ __forceinline__ uint32_t sw(int row, int c16) {
    return (uint32_t)(row * 64 + ((c16 ^ ((row ^ (row >> 2)) & 3)) << 4));
}

// fast exp, FFMA-only, fp32-class (for stats path). x <= 0.
__device__ __forceinline__ float fexp(float x) {
    x = fmaxf(x, -80.0f);
    float nf = fmaf(x, 1.4426950408889634f, 12582912.0f);
    int  i   = __float_as_int(nf) - 0x4B400000;
    float n  = nf - 12582912.0f;
    float f  = fmaf(n, -0.693145751953125f, x);
    f        = fmaf(n, -1.42860682030941723e-6f, f);
    float p = 1.3888889e-3f;
    p = fmaf(p, f, 8.3333333e-3f);
    p = fmaf(p, f, 4.1666668e-2f);
    p = fmaf(p, f, 1.6666667e-1f);
    p = fmaf(p, f, 5.0e-1f);
    p = fmaf(p, f, 1.0f);
    p = fmaf(p, f, 1.0f);
    return p * __int_as_float((i + 127) << 23);
}

// degree-4 exp, fp16-accuracy (4e-5 rel). x <= 0.
__device__ __forceinline__ float fexp4(float x) {
    x = fmaxf(x, -80.0f);
    float nf = fmaf(x, 1.4426950408889634f, 12582912.0f);
    int  i   = __float_as_int(nf) - 0x4B400000;
    float n  = nf - 12582912.0f;
    float f  = fmaf(n, -0.6931471805599453f, x);
    float p = 4.1666668e-2f;
    p = fmaf(p, f, 1.6666667e-1f);
    p = fmaf(p, f, 5.0e-1f);
    p = fmaf(p, f, 1.0f);
    p = fmaf(p, f, 1.0f);
    return p * __int_as_float((i + 127) << 23);
}

// ======================= 1-pass MMA stage: A@0, B@8192 =======================
__device__ __forceinline__ void compute_stage1(uint32_t sb, int mw0, int nw0,
                                               float cacc[4][4][4], int lane) {
    int arow = lane & 15, asel = lane >> 4;
    int brow = (lane & 7) + ((lane >> 4) << 3), bsel = (lane >> 3) & 1;
#pragma unroll
    for (int ks = 0; ks < 2; ks++) {
        uint32_t ah[4][4], bh[2][4];
#pragma unroll
        for (int mi = 0; mi < 4; mi++)
            ldsm_x4(ah[mi][0], ah[mi][1], ah[mi][2], ah[mi][3],
                    sb + sw(mw0 + mi*16 + arow, ks*2 + asel));
#pragma unroll
        for (int nb = 0; nb < 2; nb++)
            ldsm_x4(bh[nb][0], bh[nb][1], bh[nb][2], bh[nb][3],
                    sb + 8192 + sw(nw0 + nb*16 + brow, ks*2 + bsel));
#pragma unroll
        for (int mi = 0; mi < 4; mi++)
#pragma unroll
            for (int nj = 0; nj < 4; nj++)
                mma16816(cacc[mi][nj], ah[mi], bh[nj>>1][(nj&1)*2], bh[nj>>1][(nj&1)*2+1]);
    }
}

// cp.async staging (A + B), 256 threads, ld = D_
__device__ __forceinline__ void stage2L(uint32_t sb,
                                        const __half* __restrict__ Ah, size_t ar0,
                                        const __half* __restrict__ Bh, size_t br0, int k0) {
    int t = threadIdx.x;
#pragma unroll
    for (int i = 0; i < 2; i++) {
        int c = t + 256*i;
        int row = c >> 2, c16 = c & 3;
        uint32_t so = sw(row, c16);
        size_t ka = (size_t)k0 + c16*8;
        cp16(sb + so,        Ah + (ar0 + row)*(size_t)D_ + ka);
        cp16(sb + 8192 + so, Bh + (br0 + row)*(size_t)D_ + ka);
    }
}

// ======================= prep: cvt + weight transpose + positional ===========
#define NP2 ((size_t)R_*D_/2)
#define NV2 ((size_t)RQ_*D_/2)
#define NB_CVT ((unsigned)((NP2 + NV2 + 255)/256))
#define NB_WT  768u
#define NB_PV  ((unsigned)(R_/256))
__global__ void prep_kernel(const float* __restrict__ P, const float* __restrict__ VF,
                            const float* __restrict__ Wq, const float* __restrict__ Wk,
                            const float* __restrict__ Wv,
                            const float* __restrict__ p_xyz, const float* __restrict__ v_xyz,
                            const float* __restrict__ Wp1, const float* __restrict__ bp1,
                            const float* __restrict__ ln_w, const float* __restrict__ ln_b) {
    unsigned blk = blockIdx.x;
    if (blk < NB_CVT) {
        size_t i = (size_t)blk * 256 + threadIdx.x;
        const float* src; __half* hi; size_t j;
        if (i < NP2)            { src = P;  hi = g_ph;  j = i; }
        else if (i < NP2 + NV2) { src = VF; hi = g_vfh; j = i - NP2; }
        else return;
        float2 v = reinterpret_cast<const float2*>(src)[j];
        reinterpret_cast<__half2*>(hi)[j] =
            __halves2half2(__float2half_rn(v.x), __float2half_rn(v.y));
        return;
    }
    blk -= NB_CVT;
    if (blk < NB_WT) {
        int i = blk * 256 + threadIdx.x;   // 3*65536
        int w = i >> 16, rem = i & 65535;
        int d = rem >> 8, c = rem & 255;
        const float* W = (w == 0) ? Wq : (w == 1) ? Wk : Wv;
        __half* Th = (w == 0) ? g_wqT : (w == 1) ? g_wkT : g_wvT;
        Th[c*256 + d] = __float2half_rn(W[rem]);
        return;
    }
    blk -= NB_WT;
    {
        int idx = blk * 256 + threadIdx.x;
        int b = idx / N_;
        float d0 = fabsf(p_xyz[idx*3+0] - v_xyz[b*3+0]);
        float d1 = fabsf(p_xyz[idx*3+1] - v_xyz[b*3+1]);
        float d2 = fabsf(p_xyz[idx*3+2] - v_xyz[b*3+2]);
        float h0 = d0*Wp1[0] + d1*Wp1[3] + d2*Wp1[6] + bp1[0];
        float h1 = d0*Wp1[1] + d1*Wp1[4] + d2*Wp1[7] + bp1[1];
        float h2 = d0*Wp1[2] + d1*Wp1[5] + d2*Wp1[8] + bp1[2];
        float mu = (h0 + h1 + h2) * (1.0f/3.0f);
        float e0 = h0-mu, e1 = h1-mu, e2 = h2-mu;
        float inv = rsqrtf((e0*e0 + e1*e1 + e2*e2) * (1.0f/3.0f) + 1e-5f);
        g_r[idx*3+0] = fmaxf(e0*inv*ln_w[0] + ln_b[0], 0.0f);
        g_r[idx*3+1] = fmaxf(e1*inv*ln_w[1] + ln_b[1], 0.0f);
        g_r[idx*3+2] = fmaxf(e2*inv*ln_w[2] + ln_b[2], 0.0f);
    }
}

// ======================= fused projections (HMMA 1-pass, one launch) =========
// z=0: q = (vf@Wq + bq)/16 -> qh ; z=1: kpv = p@Wk + bk + pv -> kpvh ;
// z=2: v = p@Wv + bv -> TRANSPOSED fp16 store into g_vth
__global__ __launch_bounds__(256, 2)
void proj_mma_kernel(const float* __restrict__ bq, const float* __restrict__ bk,
                     const float* __restrict__ bv, const float* __restrict__ Wp2,
                     const float* __restrict__ bp2) {
    int mode = blockIdx.z;
    if (mode == 0 && blockIdx.y >= RQ_/128) return;
    extern __shared__ char dyn[];
    uint32_t sb = smem_u32(dyn);
    const __half *Xh, *WT; const float* bias;
    if (mode == 0)      { Xh = g_vfh; WT = g_wqT; bias = bq; }
    else if (mode == 1) { Xh = g_ph;  WT = g_wkT; bias = bk; }
    else                { Xh = g_ph;  WT = g_wvT; bias = bv; }

    size_t row0 = (size_t)blockIdx.y * 128;
    int c0 = blockIdx.x * 128;
    int lane = threadIdx.x & 31, wid = threadIdx.x >> 5;
    int mw0 = (wid >> 2) * 64, nw0 = (wid & 3) * 32;
    float cacc[4][4][4] = {};

    stage2L(sb + 0*STAGE_L, Xh, row0, WT, (size_t)c0, 0);  CP_COMMIT();
    stage2L(sb + 1*STAGE_L, Xh, row0, WT, (size_t)c0, 32); CP_COMMIT();
#pragma unroll 1
    for (int s = 0; s < 8; s++) {
        if (s < 7) CP_WAIT1(); else CP_WAIT0();
        __syncthreads();
        if (s + 2 < 8) {
            stage2L(sb + ((s+2)%3)*STAGE_L, Xh, row0, WT, (size_t)c0, (s+2)*32);
            CP_COMMIT();
        }
        compute_stage1(sb + (s%3)*STAGE_L, mw0, nw0, cacc, lane);
    }

    int g = lane >> 2, tg = lane & 3;
    if (mode != 2) {
#pragma unroll
        for (int mi = 0; mi < 4; mi++) {
#pragma unroll
            for (int half_m = 0; half_m < 2; half_m++) {
                size_t r = row0 + mw0 + mi*16 + g + half_m*8;
                float q0 = 0.f, q1 = 0.f, q2 = 0.f;
                if (mode == 1) { q0 = g_r[r*3+0]; q1 = g_r[r*3+1]; q2 = g_r[r*3+2]; }
#pragma unroll
                for (int nj = 0; nj < 4; nj++) {
#pragma unroll
                    for (int e = 0; e < 2; e++) {
                        int c = c0 + nw0 + nj*8 + tg*2 + e;
                        float v = cacc[mi][nj][half_m*2 + e] + bias[c];
                        if (mode == 1) {
                            v += q0*Wp2[c] + q1*Wp2[D_+c] + q2*Wp2[2*D_+c] + bp2[c];
                            g_kpvh[r*D_+c] = __float2half_rn(v);
                        } else {
                            g_qh[r*D_+c] = __float2half_rn(v * 0.0625f);
                        }
                    }
                }
            }
        }
    } else {
        // v: transpose through smem (tile T[c_local][r_local], stride 132 halves)
        __syncthreads();   // mainloop smem reads done; reuse dyn
        __half* T = reinterpret_cast<__half*>(dyn);
#pragma unroll
        for (int mi = 0; mi < 4; mi++)
#pragma unroll
            for (int half_m = 0; half_m < 2; half_m++) {
                int rl = mw0 + mi*16 + g + half_m*8;
#pragma unroll
                for (int nj = 0; nj < 4; nj++)
#pragma unroll
                    for (int e = 0; e < 2; e++) {
                        int cl = nw0 + nj*8 + tg*2 + e;
                        float v = cacc[mi][nj][half_m*2 + e] + bias[c0 + cl];
                        T[cl*132 + rl] = __float2half_rn(v);
                    }
            }
        __syncthreads();
        int b = (int)(row0 >> 14);          // row0 / N_
        int nloc = (int)(row0 & (N_-1));
        int t = threadIdx.x;
        int cl = t >> 1, seg = t & 1;       // 64 halves per thread
        __half* dst = g_vth + (size_t)(b*D_ + c0 + cl)*N_ + nloc + seg*64;
        const __half* srcp = T + cl*132 + seg*64;
#pragma unroll
        for (int j = 0; j < 8; j++) {
            uint4 v4;
            v4.x = *reinterpret_cast<const uint32_t*>(srcp + j*8 + 0);
            v4.y = *reinterpret_cast<const uint32_t*>(srcp + j*8 + 2);
            v4.z = *reinterpret_cast<const uint32_t*>(srcp + j*8 + 4);
            v4.w = *reinterpret_cast<const uint32_t*>(srcp + j*8 + 6);
            *reinterpret_cast<uint4*>(dst + j*8) = v4;
        }
    }
}

// ======================= logits (HMMA 1-pass) -> fp16 tile-exp weights =======
__global__ __launch_bounds__(256, 2)
void logits_mma_kernel() {
    extern __shared__ char dyn[];
    uint32_t sb = smem_u32(dyn);
    int b = blockIdx.z;
    int n0 = blockIdx.x * 128, m0 = blockIdx.y * 128;
    size_t ar0 = (size_t)b*M_ + m0, br0 = (size_t)b*N_ + n0;
    int lane = threadIdx.x & 31, wid = threadIdx.x >> 5;
    int mw0 = (wid >> 2) * 64, nw0 = (wid & 3) * 32;
    float cacc[4][4][4] = {};

    stage2L(sb + 0*STAGE_L, g_qh, ar0, g_kpvh, br0, 0);  CP_COMMIT();
    stage2L(sb + 1*STAGE_L, g_qh, ar0, g_kpvh, br0, 32); CP_COMMIT();
#pragma unroll 1
    for (int s = 0; s < 8; s++) {
        if (s < 7) CP_WAIT1(); else CP_WAIT0();
        __syncthreads();
        if (s + 2 < 8) {
            stage2L(sb + ((s+2)%3)*STAGE_L, g_qh, ar0, g_kpvh, br0, (s+2)*32);
            CP_COMMIT();
        }
        compute_stage1(sb + (s%3)*STAGE_L, mw0, nw0, cacc, lane);
    }

    int g = lane >> 2, tg = lane & 3;
    float* smax = reinterpret_cast<float*>(dyn);        // [2][128]
    float* ssum = smax + 256;                            // [2][128]
    __syncthreads();   // mainloop smem reads done; reuse dyn

    // phase 1: per-warp (64-row) column maxes
#pragma unroll
    for (int nj = 0; nj < 4; nj++) {
#pragma unroll
        for (int ec = 0; ec < 2; ec++) {
            float mx = -1e30f;
#pragma unroll
            for (int mi = 0; mi < 4; mi++) {
                mx = fmaxf(mx, cacc[mi][nj][ec]);
                mx = fmaxf(mx, cacc[mi][nj][2 + ec]);
            }
            mx = fmaxf(mx, __shfl_xor_sync(0xFFFFFFFFu, mx, 4));
            mx = fmaxf(mx, __shfl_xor_sync(0xFFFFFFFFu, mx, 8));
            mx = fmaxf(mx, __shfl_xor_sync(0xFFFFFFFFu, mx, 16));
            if (g == 0) {
                int nc = (wid & 3)*32 + nj*8 + tg*2 + ec;
                smax[(wid >> 2)*128 + nc] = mx;
            }
        }
    }
    __syncthreads();

    // phase 2: w = exp(l - tile_col_max) (deg-4), store fp16, accumulate sums
    __half* W = g_wexp + (size_t)b*M_*N_;
#pragma unroll
    for (int nj = 0; nj < 4; nj++) {
        int ncb = (wid & 3)*32 + nj*8 + tg*2;
        float mx0 = fmaxf(smax[ncb],     smax[128 + ncb]);
        float mx1 = fmaxf(smax[ncb + 1], smax[128 + ncb + 1]);
        float s0 = 0.0f, s1 = 0.0f;
#pragma unroll
        for (int mi = 0; mi < 4; mi++) {
#pragma unroll
            for (int hm = 0; hm < 2; hm++) {
                float w0 = fexp4(cacc[mi][nj][hm*2 + 0] - mx0);
                float w1 = fexp4(cacc[mi][nj][hm*2 + 1] - mx1);
                s0 += w0; s1 += w1;
                int m = m0 + mw0 + mi*16 + g + hm*8;
                *reinterpret_cast<__half2*>(&W[(size_t)m*N_ + n0 + ncb]) =
                    __halves2half2(__float2half_rn(w0), __float2half_rn(w1));
            }
        }
        s0 += __shfl_xor_sync(0xFFFFFFFFu, s0, 4);
        s0 += __shfl_xor_sync(0xFFFFFFFFu, s0, 8);
        s0 += __shfl_xor_sync(0xFFFFFFFFu, s0, 16);
        s1 += __shfl_xor_sync(0xFFFFFFFFu, s1, 4);
        s1 += __shfl_xor_sync(0xFFFFFFFFu, s1, 8);
        s1 += __shfl_xor_sync(0xFFFFFFFFu, s1, 16);
        if (g == 0) {
            ssum[(wid >> 2)*128 + ncb]     = s0;
            ssum[(wid >> 2)*128 + ncb + 1] = s1;
        }
    }
    __syncthreads();
    int t = threadIdx.x;
    if (t < 128) {
        int col = b*N_ + n0 + t;
        g_pmax[blockIdx.y*(B_*N_) + col] = fmaxf(smax[t], smax[128 + t]);
        g_psum[blockIdx.y*(B_*N_) + col] = ssum[t] + ssum[128 + t];
    }
}

// ======================= stats reduce -> per-tile scale factors ==============
__global__ void cstat_reduce_kernel() {
    int col = blockIdx.x * blockDim.x + threadIdx.x;   // 0..B*N-1
    float pm[NMT];
    float mx = -1e30f, sum = 0.0f;
#pragma unroll
    for (int ti = 0; ti < NMT; ti++) {
        float m2 = g_pmax[ti*(B_*N_) + col];
        float s2 = g_psum[ti*(B_*N_) + col];
        pm[ti] = m2;
        if (m2 > mx) { sum = sum * fexp(mx - m2) + s2; mx = m2; }
        else         { sum += s2 * fexp(m2 - mx); }
    }
    float cs = mx + __logf(sum);
#pragma unroll
    for (int ti = 0; ti < NMT; ti++)
        g_sfact[ti*(B_*N_) + col] = __float2half_rn(fexp(pm[ti] - cs));
}

// ======================= weighted value (HMMA 1-pass, fp16 weights) ==========
__global__ __launch_bounds__(256, 2)
void wv_mma_kernel() {
    extern __shared__ char dyn[];
    uint32_t sb = smem_u32(dyn);
    int z = blockIdx.z, b = z >> 2, sp = z & 3;
    int d0 = blockIdx.x * 128, m0 = blockIdx.y * 128;
    int kbeg = sp * KR_;
    const __half* Wx = g_wexp + (size_t)b*M_*N_;
    const __half* SF = g_sfact + ((size_t)blockIdx.y*B_ + b)*N_;
    size_t br0 = (size_t)b*D_ + d0;
    int t = threadIdx.x, lane = t & 31, wid = t >> 5;
    int mw0 = (wid >> 2) * 64, nw0 = (wid & 3) * 32;
    float cacc[4][4][4] = {};

    int rows[2], c16s[2];
#pragma unroll
    for (int i = 0; i < 2; i++) { int c = t + 256*i; rows[i] = c >> 2; c16s[i] = c & 3; }

    uint4 wraw[2];
#pragma unroll
    for (int i = 0; i < 2; i++)
        wraw[i] = *reinterpret_cast<const uint4*>(
            Wx + (size_t)(m0 + rows[i])*N_ + kbeg + c16s[i]*8);
#pragma unroll
    for (int st = 0; st < 2; st++) {
        uint32_t bufB = sb + st*STAGE_L;
#pragma unroll
        for (int i = 0; i < 2; i++) {
            uint32_t so = sw(rows[i], c16s[i]);
            size_t ka = (size_t)(kbeg + st*32) + c16s[i]*8;
            cp16(bufB + 8192 + so, g_vth + (br0 + rows[i])*(size_t)N_ + ka);
        }
        CP_COMMIT();
    }

    const int NCH = KR_ / 32;   // 128
#pragma unroll 1
    for (int s = 0; s < NCH; s++) {
        uint32_t buf  = sb + (s%3)*STAGE_L;
        char*    bufp = dyn + (s%3)*STAGE_L;
        if (s < NCH-1) CP_WAIT1(); else CP_WAIT0();
#pragma unroll
        for (int i = 0; i < 2; i++) {
            int kabs = kbeg + s*32 + c16s[i]*8;
            uint4 sf4 = *reinterpret_cast<const uint4*>(SF + kabs);
            const __half2* wp = reinterpret_cast<const __half2*>(&wraw[i]);
            const __half2* sp = reinterpret_cast<const __half2*>(&sf4);
            uint4 outv;
            __half2* op = reinterpret_cast<__half2*>(&outv);
            op[0] = __hmul2(wp[0], sp[0]);
            op[1] = __hmul2(wp[1], sp[1]);
            op[2] = __hmul2(wp[2], sp[2]);
            op[3] = __hmul2(wp[3], sp[3]);
            uint32_t so = sw(rows[i], c16s[i]);
            *reinterpret_cast<uint4*>(bufp + so) = outv;
        }
        __syncthreads();
        if (s + 1 < NCH) {
            int kn = kbeg + (s+1)*32;
#pragma unroll
            for (int i = 0; i < 2; i++)
                wraw[i] = *reinterpret_cast<const uint4*>(
                    Wx + (size_t)(m0 + rows[i])*N_ + kn + c16s[i]*8);
        }
        if (s + 2 < NCH) {
            uint32_t nbuf = sb + ((s+2)%3)*STAGE_L;
            int kn2 = kbeg + (s+2)*32;
#pragma unroll
            for (int i = 0; i < 2; i++) {
                uint32_t so = sw(rows[i], c16s[i]);
                size_t ka = (size_t)kn2 + c16s[i]*8;
                cp16(nbuf + 8192 + so, g_vth + (br0 + rows[i])*(size_t)N_ + ka);
            }
            CP_COMMIT();
        }
        compute_stage1(buf, mw0, nw0, cacc, lane);
    }

    int g = lane >> 2, tg = lane & 3;
    float* P = g_part + (size_t)z*M_*D_;
#pragma unroll
    for (int mi = 0; mi < 4; mi++)
#pragma unroll
        for (int nj = 0; nj < 4; nj++) {
            int m = m0 + mw0 + mi*16 + g;
            int d = d0 + nw0 + nj*8 + tg*2;
            float2 v0 = { cacc[mi][nj][0], cacc[mi][nj][1] };
            float2 v1 = { cacc[mi][nj][2], cacc[mi][nj][3] };
            *reinterpret_cast<float2*>(&P[(size_t)m*D_ + d])     = v0;
            *reinterpret_cast<float2*>(&P[(size_t)(m+8)*D_ + d]) = v1;
        }
}

// ======================= reduce + residual ===================================
__global__ void reduce_kernel(const float* __restrict__ Vf, float* __restrict__ out) {
    int i4 = blockIdx.x * blockDim.x + threadIdx.x;   // RQ_*D_/4
    int row = i4 >> 6;
    int b = row >> 11;
    int mrow = row & (M_ - 1);
    int d4 = i4 & 63;
    float4 acc = reinterpret_cast<const float4*>(Vf)[i4];
#pragma unroll
    for (int s = 0; s < NSPLIT; s++) {
        size_t pi = ((size_t)(b*NSPLIT + s)*M_ + mrow)*64 + d4;
        float4 p = reinterpret_cast<const float4*>(g_part)[pi];
        acc.x += p.x; acc.y += p.y; acc.z += p.z; acc.w += p.w;
    }
    reinterpret_cast<float4*>(out)[i4] = acc;
}

// ======================= launcher ============================================
extern "C" void kernel_launch(void* const* d_in, const int* in_sizes, int n_in,
                              void* d_out, int out_size) {
    const float* p_xyz      = (const float*)d_in[0];
    const float* v_xyz      = (const float*)d_in[1];
    const float* p_features = (const float*)d_in[2];
    const float* v_features = (const float*)d_in[3];
    const float* Wq  = (const float*)d_in[4];
    const float* bq  = (const float*)d_in[5];
    const float* Wk  = (const float*)d_in[6];
    const float* bk  = (const float*)d_in[7];
    const float* Wv  = (const float*)d_in[8];
    const float* bv  = (const float*)d_in[9];
    const float* Wp1 = (const float*)d_in[10];
    const float* bp1 = (const float*)d_in[11];
    const float* ln_w = (const float*)d_in[12];
    const float* ln_b = (const float*)d_in[13];
    const float* Wp2 = (const float*)d_in[14];
    const float* bp2 = (const float*)d_in[15];
    float* out = (float*)d_out;

    static int attr_done = 0;
    if (!attr_done) {
        cudaFuncSetAttribute(proj_mma_kernel,   cudaFuncAttributeMaxDynamicSharedMemorySize, DYN_SMEM_L);
        cudaFuncSetAttribute(logits_mma_kernel, cudaFuncAttributeMaxDynamicSharedMemorySize, DYN_SMEM_L);
        cudaFuncSetAttribute(wv_mma_kernel,     cudaFuncAttributeMaxDynamicSharedMemorySize, DYN_SMEM_L);
        attr_done = 1;
    }

    // [0] prep: fp16 converts + weight transpose + positional path
    prep_kernel<<<NB_CVT + NB_WT + NB_PV, 256>>>(p_features, v_features, Wq, Wk, Wv,
                                                 p_xyz, v_xyz, Wp1, bp1, ln_w, ln_b);
    // [1] fused projections q/k/v (1-pass) + fused V transpose
    proj_mma_kernel<<<dim3(2, R_/128, 3), 256, DYN_SMEM_L>>>(bq, bk, bv, Wp2, bp2);
    // [2] logits (1-pass) -> fp16 tile-exp weights + partial stats
    logits_mma_kernel<<<dim3(N_/128, M_/128, B_), 256, DYN_SMEM_L>>>();
    // [3] stats reduce -> per-tile fp16 scale factors
    cstat_reduce_kernel<<<(B_*N_)/256, 256>>>();
    // [4] weighted value (1-pass, fp16 weights * sfact, split-K=4)
    wv_mma_kernel<<<dim3(D_/128, M_/128, B_*NSPLIT), 256, DYN_SMEM_L>>>();
    // [5] reduce + residual
    reduce_kernel<<<(RQ_*D_/4)/256, 256>>>(v_features, out);
}

// round 12
// speedup vs baseline: 2.1505x; 1.0493x over previous
#include <cuda_runtime.h>
#include <cuda_fp16.h>
#include <stdint.h>
#include <math.h>

#define B_  2
#define N_  16384
#define M_  2048
#define D_  256
#define R_  (B_*N_)
#define RQ_ (B_*M_)
#define NSPLIT 4
#define KR_ (N_/NSPLIT)          // 4096 contraction per wv split
#define NMT 16                   // number of m-tiles (M_/128)
#define STAGE 32768              // A0(8K) A1(8K) B0(8K) B1(8K)  (K-chunk 64)
#define DYN_SMEM (3*STAGE)       // 96 KB

// ======================= device scratch =====================================
__device__ __align__(16) float  g_r[R_*3];
__device__ __align__(16) __half g_ph [(size_t)R_*D_];
__device__ __align__(16) __half g_vfh[(size_t)RQ_*D_];
__device__ __align__(16) __half g_wqT[D_*D_], g_wkT[D_*D_], g_wvT[D_*D_];
__device__ __align__(16) __half g_qh [(size_t)RQ_*D_];        // pre-scaled by 1/16
__device__ __align__(16) __half g_kpvh[(size_t)R_*D_];
__device__ __align__(16) __half g_vth[(size_t)B_*D_*N_];
__device__ __align__(16) __half g_wexp[(size_t)B_*M_*N_];     // 128 MB: exp(l - m_tile)
__device__ __align__(16) __half g_sfact[NMT*B_*N_];           // exp(m_tile - cstat)
__device__ __align__(16) float  g_pmax[NMT*B_*N_], g_psum[NMT*B_*N_];
__device__ __align__(16) float  g_part[(size_t)B_*NSPLIT*M_*D_];

// ======================= small helpers ======================================
__device__ __forceinline__ uint32_t smem_u32(const void* p) {
    uint32_t a;
    asm("{ .reg .u64 t; cvta.to.shared.u64 t, %1; cvt.u32.u64 %0, t; }" : "=r"(a) : "l"(p));
    return a;
}
__device__ __forceinline__ void cp16(uint32_t dst, const void* src) {
    asm volatile("cp.async.cg.shared.global [%0], [%1], 16;" :: "r"(dst), "l"(src));
}
#define CP_COMMIT() asm volatile("cp.async.commit_group;" ::: "memory")
#define CP_WAIT0()  asm volatile("cp.async.wait_group 0;" ::: "memory")
#define CP_WAIT1()  asm volatile("cp.async.wait_group 1;" ::: "memory")

__device__ __forceinline__ void ldsm_x4(uint32_t& r0, uint32_t& r1, uint32_t& r2, uint32_t& r3,
                                        uint32_t addr) {
    asm volatile("ldmatrix.sync.aligned.m8n8.x4.shared.b16 {%0,%1,%2,%3}, [%4];"
                 : "=r"(r0), "=r"(r1), "=r"(r2), "=r"(r3) : "r"(addr));
}
__device__ __forceinline__ void mma16816(float* c, const uint32_t* a, uint32_t b0, uint32_t b1) {
    asm volatile(
        "mma.sync.aligned.m16n8k16.row.col.f32.f16.f16.f32 "
        "{%0,%1,%2,%3}, {%4,%5,%6,%7}, {%8,%9}, {%0,%1,%2,%3};"
        : "+f"(c[0]), "+f"(c[1]), "+f"(c[2]), "+f"(c[3])
        : "r"(a[0]), "r"(a[1]), "r"(a[2]), "r"(a[3]), "r"(b0), "r"(b1));
}

// swizzled byte offset in a 128-row x 32-half tile (64B rows)
__device__ __forceinline__ uint32_t sw(int row, int c16) {
    return (uint32_t)(row * 64 + ((c16 ^ ((row ^ (row >> 2)) & 3)) << 4));
}

// fast exp, FFMA-only, fp32-class (stats path). x <= 0.
__device__ __forceinline__ float fexp(float x) {
    x = fmaxf(x, -80.0f);
    float nf = fmaf(x, 1.4426950408889634f, 12582912.0f);
    int  i   = __float_as_int(nf) - 0x4B400000;
    float n  = nf - 12582912.0f;
    float f  = fmaf(n, -0.693145751953125f, x);
    f        = fmaf(n, -1.42860682030941723e-6f, f);
    float p = 1.3888889e-3f;
    p = fmaf(p, f, 8.3333333e-3f);
    p = fmaf(p, f, 4.1666668e-2f);
    p = fmaf(p, f, 1.6666667e-1f);
    p = fmaf(p, f, 5.0e-1f);
    p = fmaf(p, f, 1.0f);
    p = fmaf(p, f, 1.0f);
    return p * __int_as_float((i + 127) << 23);
}

// degree-4 exp, fp16-accuracy (4e-5 rel). x <= 0.
__device__ __forceinline__ float fexp4(float x) {
    x = fmaxf(x, -80.0f);
    float nf = fmaf(x, 1.4426950408889634f, 12582912.0f);
    int  i   = __float_as_int(nf) - 0x4B400000;
    float n  = nf - 12582912.0f;
    float f  = fmaf(n, -0.6931471805599453f, x);
    float p = 4.1666668e-2f;
    p = fmaf(p, f, 1.6666667e-1f);
    p = fmaf(p, f, 5.0e-1f);
    p = fmaf(p, f, 1.0f);
    p = fmaf(p, f, 1.0f);
    return p * __int_as_float((i + 127) << 23);
}

// ======================= 1-pass MMA over one 32-K sub-tile ===================
__device__ __forceinline__ void compute_sub(uint32_t sa, uint32_t sbb, int mw0, int nw0,
                                            float cacc[4][4][4], int lane) {
    int arow = lane & 15, asel = lane >> 4;
    int brow = (lane & 7) + ((lane >> 4) << 3), bsel = (lane >> 3) & 1;
#pragma unroll
    for (int ks = 0; ks < 2; ks++) {
        uint32_t ah[4][4], bh[2][4];
#pragma unroll
        for (int mi = 0; mi < 4; mi++)
            ldsm_x4(ah[mi][0], ah[mi][1], ah[mi][2], ah[mi][3],
                    sa + sw(mw0 + mi*16 + arow, ks*2 + asel));
#pragma unroll
        for (int nb = 0; nb < 2; nb++)
            ldsm_x4(bh[nb][0], bh[nb][1], bh[nb][2], bh[nb][3],
                    sbb + sw(nw0 + nb*16 + brow, ks*2 + bsel));
#pragma unroll
        for (int mi = 0; mi < 4; mi++)
#pragma unroll
            for (int nj = 0; nj < 4; nj++)
                mma16816(cacc[mi][nj], ah[mi], bh[nj>>1][(nj&1)*2], bh[nj>>1][(nj&1)*2+1]);
    }
}
// full 64-K stage: A0@0 A1@8192 B0@16384 B1@24576
__device__ __forceinline__ void compute_stage64(uint32_t sb, int mw0, int nw0,
                                                float cacc[4][4][4], int lane) {
    compute_sub(sb,        sb + 16384, mw0, nw0, cacc, lane);
    compute_sub(sb + 8192, sb + 24576, mw0, nw0, cacc, lane);
}

// cp.async staging of a 64-K stage (A + B), 256 threads, ld = D_
__device__ __forceinline__ void stage64(uint32_t sb,
                                        const __half* __restrict__ Ah, size_t ar0,
                                        const __half* __restrict__ Bh, size_t br0, int k0) {
    int t = threadIdx.x;
#pragma unroll
    for (int i = 0; i < 2; i++) {
        int c = t + 256*i;
        int row = c >> 2, c16 = c & 3;
        uint32_t so = sw(row, c16);
#pragma unroll
        for (int h = 0; h < 2; h++) {
            size_t ka = (size_t)k0 + h*32 + c16*8;
            cp16(sb + h*8192 + so,         Ah + (ar0 + row)*(size_t)D_ + ka);
            cp16(sb + 16384 + h*8192 + so, Bh + (br0 + row)*(size_t)D_ + ka);
        }
    }
}

// ======================= prep: cvt + weight transpose + positional ===========
#define NP2 ((size_t)R_*D_/2)
#define NV2 ((size_t)RQ_*D_/2)
#define NB_CVT ((unsigned)((NP2 + NV2 + 255)/256))
#define NB_WT  768u
#define NB_PV  ((unsigned)(R_/256))
__global__ void prep_kernel(const float* __restrict__ P, const float* __restrict__ VF,
                            const float* __restrict__ Wq, const float* __restrict__ Wk,
                            const float* __restrict__ Wv,
                            const float* __restrict__ p_xyz, const float* __restrict__ v_xyz,
                            const float* __restrict__ Wp1, const float* __restrict__ bp1,
                            const float* __restrict__ ln_w, const float* __restrict__ ln_b) {
    unsigned blk = blockIdx.x;
    if (blk < NB_CVT) {
        size_t i = (size_t)blk * 256 + threadIdx.x;
        const float* src; __half* hi; size_t j;
        if (i < NP2)            { src = P;  hi = g_ph;  j = i; }
        else if (i < NP2 + NV2) { src = VF; hi = g_vfh; j = i - NP2; }
        else return;
        float2 v = reinterpret_cast<const float2*>(src)[j];
        reinterpret_cast<__half2*>(hi)[j] =
            __halves2half2(__float2half_rn(v.x), __float2half_rn(v.y));
        return;
    }
    blk -= NB_CVT;
    if (blk < NB_WT) {
        int i = blk * 256 + threadIdx.x;   // 3*65536
        int w = i >> 16, rem = i & 65535;
        int d = rem >> 8, c = rem & 255;
        const float* W = (w == 0) ? Wq : (w == 1) ? Wk : Wv;
        __half* Th = (w == 0) ? g_wqT : (w == 1) ? g_wkT : g_wvT;
        Th[c*256 + d] = __float2half_rn(W[rem]);
        return;
    }
    blk -= NB_WT;
    {
        int idx = blk * 256 + threadIdx.x;
        int b = idx / N_;
        float d0 = fabsf(p_xyz[idx*3+0] - v_xyz[b*3+0]);
        float d1 = fabsf(p_xyz[idx*3+1] - v_xyz[b*3+1]);
        float d2 = fabsf(p_xyz[idx*3+2] - v_xyz[b*3+2]);
        float h0 = d0*Wp1[0] + d1*Wp1[3] + d2*Wp1[6] + bp1[0];
        float h1 = d0*Wp1[1] + d1*Wp1[4] + d2*Wp1[7] + bp1[1];
        float h2 = d0*Wp1[2] + d1*Wp1[5] + d2*Wp1[8] + bp1[2];
        float mu = (h0 + h1 + h2) * (1.0f/3.0f);
        float e0 = h0-mu, e1 = h1-mu, e2 = h2-mu;
        float inv = rsqrtf((e0*e0 + e1*e1 + e2*e2) * (1.0f/3.0f) + 1e-5f);
        g_r[idx*3+0] = fmaxf(e0*inv*ln_w[0] + ln_b[0], 0.0f);
        g_r[idx*3+1] = fmaxf(e1*inv*ln_w[1] + ln_b[1], 0.0f);
        g_r[idx*3+2] = fmaxf(e2*inv*ln_w[2] + ln_b[2], 0.0f);
    }
}

// ======================= fused projections (HMMA 1-pass, one launch) =========
// z=0: q = (vf@Wq + bq)/16 -> qh ; z=1: kpv = p@Wk + bk + pv -> kpvh ;
// z=2: v = p@Wv + bv -> TRANSPOSED fp16 store into g_vth
__global__ __launch_bounds__(256, 2)
void proj_mma_kernel(const float* __restrict__ bq, const float* __restrict__ bk,
                     const float* __restrict__ bv, const float* __restrict__ Wp2,
                     const float* __restrict__ bp2) {
    int mode = blockIdx.z;
    if (mode == 0 && blockIdx.y >= RQ_/128) return;
    extern __shared__ char dyn[];
    uint32_t sb = smem_u32(dyn);
    const __half *Xh, *WT; const float* bias;
    if (mode == 0)      { Xh = g_vfh; WT = g_wqT; bias = bq; }
    else if (mode == 1) { Xh = g_ph;  WT = g_wkT; bias = bk; }
    else                { Xh = g_ph;  WT = g_wvT; bias = bv; }

    size_t row0 = (size_t)blockIdx.y * 128;
    int c0 = blockIdx.x * 128;
    int lane = threadIdx.x & 31, wid = threadIdx.x >> 5;
    int mw0 = (wid >> 2) * 64, nw0 = (wid & 3) * 32;
    float cacc[4][4][4] = {};

    stage64(sb + 0*STAGE, Xh, row0, WT, (size_t)c0, 0);  CP_COMMIT();
    stage64(sb + 1*STAGE, Xh, row0, WT, (size_t)c0, 64); CP_COMMIT();
#pragma unroll 1
    for (int s = 0; s < 4; s++) {
        if (s < 3) CP_WAIT1(); else CP_WAIT0();
        __syncthreads();
        if (s + 2 < 4) {
            stage64(sb + ((s+2)%3)*STAGE, Xh, row0, WT, (size_t)c0, (s+2)*64);
            CP_COMMIT();
        }
        compute_stage64(sb + (s%3)*STAGE, mw0, nw0, cacc, lane);
    }

    int g = lane >> 2, tg = lane & 3;
    if (mode != 2) {
#pragma unroll
        for (int mi = 0; mi < 4; mi++) {
#pragma unroll
            for (int half_m = 0; half_m < 2; half_m++) {
                size_t r = row0 + mw0 + mi*16 + g + half_m*8;
                float q0 = 0.f, q1 = 0.f, q2 = 0.f;
                if (mode == 1) { q0 = g_r[r*3+0]; q1 = g_r[r*3+1]; q2 = g_r[r*3+2]; }
#pragma unroll
                for (int nj = 0; nj < 4; nj++) {
#pragma unroll
                    for (int e = 0; e < 2; e++) {
                        int c = c0 + nw0 + nj*8 + tg*2 + e;
                        float v = cacc[mi][nj][half_m*2 + e] + bias[c];
                        if (mode == 1) {
                            v += q0*Wp2[c] + q1*Wp2[D_+c] + q2*Wp2[2*D_+c] + bp2[c];
                            g_kpvh[r*D_+c] = __float2half_rn(v);
                        } else {
                            g_qh[r*D_+c] = __float2half_rn(v * 0.0625f);
                        }
                    }
                }
            }
        }
    } else {
        // v: transpose through smem (tile T[c_local][r_local], stride 132 halves)
        __syncthreads();
        __half* T = reinterpret_cast<__half*>(dyn);
#pragma unroll
        for (int mi = 0; mi < 4; mi++)
#pragma unroll
            for (int half_m = 0; half_m < 2; half_m++) {
                int rl = mw0 + mi*16 + g + half_m*8;
#pragma unroll
                for (int nj = 0; nj < 4; nj++)
#pragma unroll
                    for (int e = 0; e < 2; e++) {
                        int cl = nw0 + nj*8 + tg*2 + e;
                        float v = cacc[mi][nj][half_m*2 + e] + bias[c0 + cl];
                        T[cl*132 + rl] = __float2half_rn(v);
                    }
            }
        __syncthreads();
        int b = (int)(row0 >> 14);
        int nloc = (int)(row0 & (N_-1));
        int t = threadIdx.x;
        int cl = t >> 1, seg = t & 1;
        __half* dst = g_vth + (size_t)(b*D_ + c0 + cl)*N_ + nloc + seg*64;
        const __half* srcp = T + cl*132 + seg*64;
#pragma unroll
        for (int j = 0; j < 8; j++) {
            uint4 v4;
            v4.x = *reinterpret_cast<const uint32_t*>(srcp + j*8 + 0);
            v4.y = *reinterpret_cast<const uint32_t*>(srcp + j*8 + 2);
            v4.z = *reinterpret_cast<const uint32_t*>(srcp + j*8 + 4);
            v4.w = *reinterpret_cast<const uint32_t*>(srcp + j*8 + 6);
            *reinterpret_cast<uint4*>(dst + j*8) = v4;
        }
    }
}

// ======================= logits (HMMA 1-pass) -> fp16 tile-exp weights =======
__global__ __launch_bounds__(256, 2)
void logits_mma_kernel() {
    extern __shared__ char dyn[];
    uint32_t sb = smem_u32(dyn);
    int b = blockIdx.z;
    int n0 = blockIdx.x * 128, m0 = blockIdx.y * 128;
    size_t ar0 = (size_t)b*M_ + m0, br0 = (size_t)b*N_ + n0;
    int lane = threadIdx.x & 31, wid = threadIdx.x >> 5;
    int mw0 = (wid >> 2) * 64, nw0 = (wid & 3) * 32;
    float cacc[4][4][4] = {};

    stage64(sb + 0*STAGE, g_qh, ar0, g_kpvh, br0, 0);  CP_COMMIT();
    stage64(sb + 1*STAGE, g_qh, ar0, g_kpvh, br0, 64); CP_COMMIT();
#pragma unroll 1
    for (int s = 0; s < 4; s++) {
        if (s < 3) CP_WAIT1(); else CP_WAIT0();
        __syncthreads();
        if (s + 2 < 4) {
            stage64(sb + ((s+2)%3)*STAGE, g_qh, ar0, g_kpvh, br0, (s+2)*64);
            CP_COMMIT();
        }
        compute_stage64(sb + (s%3)*STAGE, mw0, nw0, cacc, lane);
    }

    int g = lane >> 2, tg = lane & 3;
    float* smax = reinterpret_cast<float*>(dyn);        // [2][128]
    float* ssum = smax + 256;                            // [2][128]
    __syncthreads();

    // phase 1: per-warp (64-row) column maxes
#pragma unroll
    for (int nj = 0; nj < 4; nj++) {
#pragma unroll
        for (int ec = 0; ec < 2; ec++) {
            float mx = -1e30f;
#pragma unroll
            for (int mi = 0; mi < 4; mi++) {
                mx = fmaxf(mx, cacc[mi][nj][ec]);
                mx = fmaxf(mx, cacc[mi][nj][2 + ec]);
            }
            mx = fmaxf(mx, __shfl_xor_sync(0xFFFFFFFFu, mx, 4));
            mx = fmaxf(mx, __shfl_xor_sync(0xFFFFFFFFu, mx, 8));
            mx = fmaxf(mx, __shfl_xor_sync(0xFFFFFFFFu, mx, 16));
            if (g == 0) {
                int nc = (wid & 3)*32 + nj*8 + tg*2 + ec;
                smax[(wid >> 2)*128 + nc] = mx;
            }
        }
    }
    __syncthreads();

    // phase 2: w = exp(l - tile_col_max) (deg-4), store fp16, accumulate sums
    __half* W = g_wexp + (size_t)b*M_*N_;
#pragma unroll
    for (int nj = 0; nj < 4; nj++) {
        int ncb = (wid & 3)*32 + nj*8 + tg*2;
        float mx0 = fmaxf(smax[ncb],     smax[128 + ncb]);
        float mx1 = fmaxf(smax[ncb + 1], smax[128 + ncb + 1]);
        float s0 = 0.0f, s1 = 0.0f;
#pragma unroll
        for (int mi = 0; mi < 4; mi++) {
#pragma unroll
            for (int hm = 0; hm < 2; hm++) {
                float w0 = fexp4(cacc[mi][nj][hm*2 + 0] - mx0);
                float w1 = fexp4(cacc[mi][nj][hm*2 + 1] - mx1);
                s0 += w0; s1 += w1;
                int m = m0 + mw0 + mi*16 + g + hm*8;
                *reinterpret_cast<__half2*>(&W[(size_t)m*N_ + n0 + ncb]) =
                    __halves2half2(__float2half_rn(w0), __float2half_rn(w1));
            }
        }
        s0 += __shfl_xor_sync(0xFFFFFFFFu, s0, 4);
        s0 += __shfl_xor_sync(0xFFFFFFFFu, s0, 8);
        s0 += __shfl_xor_sync(0xFFFFFFFFu, s0, 16);
        s1 += __shfl_xor_sync(0xFFFFFFFFu, s1, 4);
        s1 += __shfl_xor_sync(0xFFFFFFFFu, s1, 8);
        s1 += __shfl_xor_sync(0xFFFFFFFFu, s1, 16);
        if (g == 0) {
            ssum[(wid >> 2)*128 + ncb]     = s0;
            ssum[(wid >> 2)*128 + ncb + 1] = s1;
        }
    }
    __syncthreads();
    int t = threadIdx.x;
    if (t < 128) {
        int col = b*N_ + n0 + t;
        g_pmax[blockIdx.y*(B_*N_) + col] = fmaxf(smax[t], smax[128 + t]);
        g_psum[blockIdx.y*(B_*N_) + col] = ssum[t] + ssum[128 + t];
    }
}

// ======================= stats reduce -> per-tile scale factors ==============
// 2-way split per column: thread pair (via shfl) each handles 8 of 16 tiles.
__global__ void cstat_reduce_kernel() {
    int gid = blockIdx.x * blockDim.x + threadIdx.x;   // 0..2*B*N-1
    int col = gid >> 1, h = gid & 1;
    float pm[8];
    float mx = -1e30f, sum = 0.0f;
#pragma unroll
    for (int u = 0; u < 8; u++) {
        int ti = h*8 + u;
        float m2 = g_pmax[ti*(B_*N_) + col];
        float s2 = g_psum[ti*(B_*N_) + col];
        pm[u] = m2;
        if (m2 > mx) { sum = sum * fexp(mx - m2) + s2; mx = m2; }
        else         { sum += s2 * fexp(m2 - mx); }
    }
    float mo = __shfl_xor_sync(0xFFFFFFFFu, mx, 1);
    float so = __shfl_xor_sync(0xFFFFFFFFu, sum, 1);
    float mm = fmaxf(mx, mo);
    float ss = sum * fexp(mx - mm) + so * fexp(mo - mm);
    float cs = mm + __logf(ss);
#pragma unroll
    for (int u = 0; u < 8; u++)
        g_sfact[(h*8 + u)*(B_*N_) + col] = __float2half_rn(fexp(pm[u] - cs));
}

// ======================= weighted value (HMMA 1-pass, fp16 weights) ==========
__global__ __launch_bounds__(256, 2)
void wv_mma_kernel() {
    extern __shared__ char dyn[];
    uint32_t sb = smem_u32(dyn);
    int z = blockIdx.z, b = z >> 2, sp = z & 3;
    int d0 = blockIdx.x * 128, m0 = blockIdx.y * 128;
    int kbeg = sp * KR_;
    const __half* Wx = g_wexp + (size_t)b*M_*N_;
    const __half* SF = g_sfact + ((size_t)blockIdx.y*B_ + b)*N_;
    size_t br0 = (size_t)b*D_ + d0;
    int t = threadIdx.x, lane = t & 31, wid = t >> 5;
    int mw0 = (wid >> 2) * 64, nw0 = (wid & 3) * 32;
    float cacc[4][4][4] = {};

    int rows[2], c16s[2];
#pragma unroll
    for (int i = 0; i < 2; i++) { int c = t + 256*i; rows[i] = c >> 2; c16s[i] = c & 3; }

    // stage layout: W0@0 W1@8192 V0@16384 V1@24576
    uint4 wraw[2][2];
#pragma unroll
    for (int h = 0; h < 2; h++)
#pragma unroll
        for (int i = 0; i < 2; i++)
            wraw[h][i] = *reinterpret_cast<const uint4*>(
                Wx + (size_t)(m0 + rows[i])*N_ + kbeg + h*32 + c16s[i]*8);
#pragma unroll
    for (int st = 0; st < 2; st++) {
        uint32_t bufB = sb + st*STAGE;
#pragma unroll
        for (int h = 0; h < 2; h++)
#pragma unroll
            for (int i = 0; i < 2; i++) {
                uint32_t so = sw(rows[i], c16s[i]);
                size_t ka = (size_t)(kbeg + st*64 + h*32) + c16s[i]*8;
                cp16(bufB + 16384 + h*8192 + so, g_vth + (br0 + rows[i])*(size_t)N_ + ka);
            }
        CP_COMMIT();
    }

    const int NCH = KR_ / 64;   // 64
#pragma unroll 1
    for (int s = 0; s < NCH; s++) {
        uint32_t buf  = sb + (s%3)*STAGE;
        char*    bufp = dyn + (s%3)*STAGE;
        if (s < NCH-1) CP_WAIT1(); else CP_WAIT0();
        // transform + STS W(s): w = w_tile * sfact (half2 muls)
#pragma unroll
        for (int h = 0; h < 2; h++)
#pragma unroll
            for (int i = 0; i < 2; i++) {
                int kabs = kbeg + s*64 + h*32 + c16s[i]*8;
                uint4 sf4 = *reinterpret_cast<const uint4*>(SF + kabs);
                const __half2* wp = reinterpret_cast<const __half2*>(&wraw[h][i]);
                const __half2* spp = reinterpret_cast<const __half2*>(&sf4);
                uint4 outv;
                __half2* op = reinterpret_cast<__half2*>(&outv);
                op[0] = __hmul2(wp[0], spp[0]);
                op[1] = __hmul2(wp[1], spp[1]);
                op[2] = __hmul2(wp[2], spp[2]);
                op[3] = __hmul2(wp[3], spp[3]);
                uint32_t so = sw(rows[i], c16s[i]);
                *reinterpret_cast<uint4*>(bufp + h*8192 + so) = outv;
            }
        __syncthreads();
        if (s + 1 < NCH) {
            int kn = kbeg + (s+1)*64;
#pragma unroll
            for (int h = 0; h < 2; h++)
#pragma unroll
                for (int i = 0; i < 2; i++)
                    wraw[h][i] = *reinterpret_cast<const uint4*>(
                        Wx + (size_t)(m0 + rows[i])*N_ + kn + h*32 + c16s[i]*8);
        }
        if (s + 2 < NCH) {
            uint32_t nbuf = sb + ((s+2)%3)*STAGE;
            int kn2 = kbeg + (s+2)*64;
#pragma unroll
            for (int h = 0; h < 2; h++)
#pragma unroll
                for (int i = 0; i < 2; i++) {
                    uint32_t so = sw(rows[i], c16s[i]);
                    size_t ka = (size_t)(kn2 + h*32) + c16s[i]*8;
                    cp16(nbuf + 16384 + h*8192 + so, g_vth + (br0 + rows[i])*(size_t)N_ + ka);
                }
            CP_COMMIT();
        }
        compute_sub(buf,        buf + 16384, mw0, nw0, cacc, lane);
        compute_sub(buf + 8192, buf + 24576, mw0, nw0, cacc, lane);
    }

    int g = lane >> 2, tg = lane & 3;
    float* P = g_part + (size_t)z*M_*D_;
#pragma unroll
    for (int mi = 0; mi < 4; mi++)
#pragma unroll
        for (int nj = 0; nj < 4; nj++) {
            int m = m0 + mw0 + mi*16 + g;
            int d = d0 + nw0 + nj*8 + tg*2;
            float2 v0 = { cacc[mi][nj][0], cacc[mi][nj][1] };
            float2 v1 = { cacc[mi][nj][2], cacc[mi][nj][3] };
            *reinterpret_cast<float2*>(&P[(size_t)m*D_ + d])     = v0;
            *reinterpret_cast<float2*>(&P[(size_t)(m+8)*D_ + d]) = v1;
        }
}

// ======================= reduce + residual ===================================
__global__ void reduce_kernel(const float* __restrict__ Vf, float* __restrict__ out) {
    int i4 = blockIdx.x * blockDim.x + threadIdx.x;   // RQ_*D_/4
    int row = i4 >> 6;
    int b = row >> 11;
    int mrow = row & (M_ - 1);
    int d4 = i4 & 63;
    float4 acc = reinterpret_cast<const float4*>(Vf)[i4];
#pragma unroll
    for (int s = 0; s < NSPLIT; s++) {
        size_t pi = ((size_t)(b*NSPLIT + s)*M_ + mrow)*64 + d4;
        float4 p = reinterpret_cast<const float4*>(g_part)[pi];
        acc.x += p.x; acc.y += p.y; acc.z += p.z; acc.w += p.w;
    }
    reinterpret_cast<float4*>(out)[i4] = acc;
}

// ======================= launcher ============================================
extern "C" void kernel_launch(void* const* d_in, const int* in_sizes, int n_in,
                              void* d_out, int out_size) {
    const float* p_xyz      = (const float*)d_in[0];
    const float* v_xyz      = (const float*)d_in[1];
    const float* p_features = (const float*)d_in[2];
    const float* v_features = (const float*)d_in[3];
    const float* Wq  = (const float*)d_in[4];
    const float* bq  = (const float*)d_in[5];
    const float* Wk  = (const float*)d_in[6];
    const float* bk  = (const float*)d_in[7];
    const float* Wv  = (const float*)d_in[8];
    const float* bv  = (const float*)d_in[9];
    const float* Wp1 = (const float*)d_in[10];
    const float* bp1 = (const float*)d_in[11];
    const float* ln_w = (const float*)d_in[12];
    const float* ln_b = (const float*)d_in[13];
    const float* Wp2 = (const float*)d_in[14];
    const float* bp2 = (const float*)d_in[15];
    float* out = (float*)d_out;

    static int attr_done = 0;
    if (!attr_done) {
        cudaFuncSetAttribute(proj_mma_kernel,   cudaFuncAttributeMaxDynamicSharedMemorySize, DYN_SMEM);
        cudaFuncSetAttribute(logits_mma_kernel, cudaFuncAttributeMaxDynamicSharedMemorySize, DYN_SMEM);
        cudaFuncSetAttribute(wv_mma_kernel,     cudaFuncAttributeMaxDynamicSharedMemorySize, DYN_SMEM);
        attr_done = 1;
    }

    // [0] prep: fp16 converts + weight transpose + positional path
    prep_kernel<<<NB_CVT + NB_WT + NB_PV, 256>>>(p_features, v_features, Wq, Wk, Wv,
                                                 p_xyz, v_xyz, Wp1, bp1, ln_w, ln_b);
    // [1] fused projections q/k/v (1-pass, K64 stages) + fused V transpose
    proj_mma_kernel<<<dim3(2, R_/128, 3), 256, DYN_SMEM>>>(bq, bk, bv, Wp2, bp2);
    // [2] logits (1-pass, K64 stages) -> fp16 tile-exp weights + partial stats
    logits_mma_kernel<<<dim3(N_/128, M_/128, B_), 256, DYN_SMEM>>>();
    // [3] stats reduce -> per-tile fp16 scale factors (2-way split)
    cstat_reduce_kernel<<<(2*B_*N_)/256, 256>>>();
    // [4] weighted value (1-pass, K64 stages, fp16 weights * sfact, split-K=4)
    wv_mma_kernel<<<dim3(D_/128, M_/128, B_*NSPLIT), 256, DYN_SMEM>>>();
    // [5] reduce + residual
    reduce_kernel<<<(RQ_*D_/4)/256, 256>>>(v_features, out);
}